// round 10
// baseline (speedup 1.0000x reference)
#include <cuda_runtime.h>
#include <stdint.h>
#include <math.h>

#define S_ 2048
#define E_ 1280
#define H_ 16
#define D_ 80
#define F_ 5120
#define E3_ 3840

// ---------------- scratch (device globals; no runtime allocation) ----------------
__device__ float g_ln[S_ * E_];
__device__ float g_qkv[S_ * E3_];
__device__ float g_q[H_ * S_ * D_];
__device__ float g_k[H_ * S_ * D_];
__device__ float g_v[H_ * S_ * D_];
__device__ float g_attn[S_ * E_];
__device__ float g_x1[S_ * E_];
__device__ float g_ln2[S_ * E_];
__device__ float g_fc1[S_ * F_];

// ---------------- helpers ----------------
__device__ __forceinline__ uint32_t f2tf(float x) {
    uint32_t r;
    asm("cvt.rna.tf32.f32 %0, %1;" : "=r"(r) : "f"(x));
    return r;
}

__device__ __forceinline__ void mma_tf32(float* c, const uint32_t* a, uint32_t b0, uint32_t b1) {
    asm volatile(
        "mma.sync.aligned.m16n8k8.row.col.f32.tf32.tf32.f32 "
        "{%0,%1,%2,%3}, {%4,%5,%6,%7}, {%8,%9}, {%0,%1,%2,%3};\n"
        : "+f"(c[0]), "+f"(c[1]), "+f"(c[2]), "+f"(c[3])
        : "r"(a[0]), "r"(a[1]), "r"(a[2]), "r"(a[3]), "r"(b0), "r"(b1));
}

// ---------------- LayerNorm ----------------
__global__ __launch_bounds__(256) void ln_kernel(const float* __restrict__ x,
                                                 const float* __restrict__ g,
                                                 const float* __restrict__ b,
                                                 float* __restrict__ out) {
    int row = blockIdx.x;
    const float* xr = x + (size_t)row * E_;
    float s = 0.f, s2 = 0.f;
    for (int i = threadIdx.x; i < E_; i += 256) {
        float v = xr[i];
        s += v; s2 += v * v;
    }
    __shared__ float sh[32];
    #pragma unroll
    for (int o = 16; o > 0; o >>= 1) {
        s  += __shfl_down_sync(0xffffffffu, s, o);
        s2 += __shfl_down_sync(0xffffffffu, s2, o);
    }
    int w = threadIdx.x >> 5, l = threadIdx.x & 31;
    if (l == 0) { sh[w] = s; sh[w + 8] = s2; }
    __syncthreads();
    if (threadIdx.x == 0) {
        float ts = 0.f, ts2 = 0.f;
        #pragma unroll
        for (int i = 0; i < 8; i++) { ts += sh[i]; ts2 += sh[i + 8]; }
        float mean = ts / E_;
        float var = ts2 / E_ - mean * mean;
        sh[16] = mean;
        sh[17] = rsqrtf(var + 1e-6f);
    }
    __syncthreads();
    float mean = sh[16], inv = sh[17];
    for (int i = threadIdx.x; i < E_; i += 256) {
        out[(size_t)row * E_ + i] = (xr[i] - mean) * inv * g[i] + b[i];
    }
}

// ---------------- tf32 tensor-core GEMM ----------------
// C[M,N] = A[M,K] @ B[K,N] + bias (+epilogue)
// MODE 0: bias only.  MODE 1: bias + quickGELU.  MODE 2: bias + residual R.
// 128x128 block tile, k-tile 16, double-buffered smem, 256 threads.
// Warp (wm,wn) owns 32x64: 2 m-tiles (m16) x 8 n-tiles (n8), mma.m16n8k8.tf32.
#define AS_STRIDE 20
#define BS_STRIDE 136
template <int MODE>
__global__ __launch_bounds__(256) void gemm_tf32(const float* __restrict__ A,
                                                 const float* __restrict__ B,
                                                 const float* __restrict__ bias,
                                                 const float* __restrict__ R,
                                                 float* __restrict__ C,
                                                 int M, int N, int K) {
    __shared__ uint32_t As[2][128 * AS_STRIDE];
    __shared__ uint32_t Bs[2][16 * BS_STRIDE];

    const int t = threadIdx.x;
    const int warp = t >> 5, lane = t & 31;
    const int g = lane >> 2, tg = lane & 3;
    const int wm = warp >> 1, wn = warp & 1;
    const int m0 = blockIdx.y * 128, n0 = blockIdx.x * 128;

    float acc[2][8][4];
    #pragma unroll
    for (int mt = 0; mt < 2; mt++)
        #pragma unroll
        for (int nt = 0; nt < 8; nt++)
            #pragma unroll
            for (int r = 0; r < 4; r++) acc[mt][nt][r] = 0.f;

    const float* Ap = A + (size_t)m0 * K;
    const float* Bp = B + n0;

    float4 ra[2], rb[2];

    // ---- LDG tile k0 ----
    #define LDG_TILE(k0)                                                              \
        {                                                                             \
            _Pragma("unroll")                                                         \
            for (int i = 0; i < 2; i++) {                                             \
                int idx = t + 256 * i;                                                \
                ra[i] = *(const float4*)(Ap + (size_t)(idx >> 2) * K + (k0) + (idx & 3) * 4); \
                rb[i] = *(const float4*)(Bp + (size_t)((k0) + (idx >> 5)) * N + (idx & 31) * 4); \
            }                                                                         \
        }

    // ---- STS to buffer ----
    #define STS_TILE(buf)                                                             \
        {                                                                             \
            _Pragma("unroll")                                                         \
            for (int i = 0; i < 2; i++) {                                             \
                int idx = t + 256 * i;                                                \
                uint4 va = make_uint4(f2tf(ra[i].x), f2tf(ra[i].y), f2tf(ra[i].z), f2tf(ra[i].w)); \
                *(uint4*)&As[buf][(idx >> 2) * AS_STRIDE + (idx & 3) * 4] = va;       \
                uint4 vb = make_uint4(f2tf(rb[i].x), f2tf(rb[i].y), f2tf(rb[i].z), f2tf(rb[i].w)); \
                *(uint4*)&Bs[buf][(idx >> 5) * BS_STRIDE + (idx & 31) * 4] = vb;      \
            }                                                                         \
        }

    const int NK = K / 16;
    LDG_TILE(0);
    STS_TILE(0);
    __syncthreads();

    for (int it = 0; it < NK; it++) {
        if (it + 1 < NK) LDG_TILE((it + 1) * 16);
        const int buf = it & 1;
        #pragma unroll
        for (int ks = 0; ks < 2; ks++) {
            uint32_t af[2][4];
            #pragma unroll
            for (int mt = 0; mt < 2; mt++) {
                const uint32_t* ab = &As[buf][(wm * 32 + mt * 16 + g) * AS_STRIDE + ks * 8 + tg];
                af[mt][0] = ab[0];
                af[mt][1] = ab[8 * AS_STRIDE];
                af[mt][2] = ab[4];
                af[mt][3] = ab[8 * AS_STRIDE + 4];
            }
            #pragma unroll
            for (int nt = 0; nt < 8; nt++) {
                const uint32_t* bb = &Bs[buf][(ks * 8 + tg) * BS_STRIDE + wn * 64 + nt * 8 + g];
                uint32_t b0 = bb[0];
                uint32_t b1 = bb[4 * BS_STRIDE];
                #pragma unroll
                for (int mt = 0; mt < 2; mt++) mma_tf32(acc[mt][nt], af[mt], b0, b1);
            }
        }
        if (it + 1 < NK) {
            STS_TILE((it + 1) & 1);
            __syncthreads();
        }
    }

    // ---- epilogue ----
    #pragma unroll
    for (int mt = 0; mt < 2; mt++) {
        int r0 = m0 + wm * 32 + mt * 16 + g;
        int r1 = r0 + 8;
        #pragma unroll
        for (int nt = 0; nt < 8; nt++) {
            int col = n0 + wn * 64 + nt * 8 + tg * 2;
            float b0 = bias[col], b1 = bias[col + 1];
            float v0 = acc[mt][nt][0] + b0;
            float v1 = acc[mt][nt][1] + b1;
            float v2 = acc[mt][nt][2] + b0;
            float v3 = acc[mt][nt][3] + b1;
            if (MODE == 1) {
                v0 = v0 / (1.f + __expf(-1.702f * v0));
                v1 = v1 / (1.f + __expf(-1.702f * v1));
                v2 = v2 / (1.f + __expf(-1.702f * v2));
                v3 = v3 / (1.f + __expf(-1.702f * v3));
            }
            if (MODE == 2) {
                float2 rr0 = *(const float2*)&R[(size_t)r0 * N + col];
                float2 rr1 = *(const float2*)&R[(size_t)r1 * N + col];
                v0 += rr0.x; v1 += rr0.y; v2 += rr1.x; v3 += rr1.y;
            }
            *(float2*)&C[(size_t)r0 * N + col] = make_float2(v0, v1);
            *(float2*)&C[(size_t)r1 * N + col] = make_float2(v2, v3);
        }
    }
}

// ---------------- RoPE + head split (q,k rotated; v copied) ----------------
__global__ __launch_bounds__(256) void rope_kernel(const float* __restrict__ qkv,
                                                   const float* __restrict__ cosp,
                                                   const float* __restrict__ sinp,
                                                   float* __restrict__ q,
                                                   float* __restrict__ k,
                                                   float* __restrict__ v) {
    int idx = blockIdx.x * 256 + threadIdx.x;
    if (idx >= S_ * H_ * D_) return;
    int d = idx % D_;
    int h = (idx / D_) % H_;
    int s = idx / (H_ * D_);
    float c = cosp[s * D_ + d], sn = sinp[s * D_ + d];
    size_t base = (size_t)s * E3_ + h * D_;
    float qv = qkv[base + d];
    float kv = qkv[base + E_ + d];
    float vv = qkv[base + 2 * E_ + d];
    int dro = (d < 40) ? d + 40 : d - 40;
    float sgn = (d < 40) ? -1.f : 1.f;
    float qr = sgn * qkv[base + dro];
    float kr = sgn * qkv[base + E_ + dro];
    size_t o = ((size_t)h * S_ + s) * D_ + d;
    q[o] = qv * c + qr * sn;
    k[o] = kv * c + kr * sn;
    v[o] = vv;
}

// ---------------- Flash attention (fp32, online softmax) ----------------
__global__ __launch_bounds__(256) void attn_kernel(const float* __restrict__ Q,
                                                   const float* __restrict__ K,
                                                   const float* __restrict__ V,
                                                   float* __restrict__ out) {
    __shared__ float Qs[32][81];
    __shared__ float Ks[32][81];
    __shared__ float Vs[32][81];
    __shared__ float Ps[32][33];
    __shared__ float mrow[32], lrow[32], arow[32];

    int h = blockIdx.y;
    int q0 = blockIdx.x * 32;
    int t = threadIdx.x;
    int ty = t >> 4, tx = t & 15;
    int r0 = ty * 2, r1 = r0 + 1;
    int c0 = tx * 2, c1 = c0 + 1;
    int oc = tx * 5;
    const size_t hb = (size_t)h * S_ * D_;

    for (int i = t; i < 32 * D_; i += 256) {
        int r = i / D_, c = i % D_;
        Qs[r][c] = Q[hb + (size_t)(q0 + r) * D_ + c];
    }
    if (t < 32) { mrow[t] = -3.0e38f; lrow[t] = 0.f; }
    float acc[2][5];
    #pragma unroll
    for (int i = 0; i < 2; i++)
        #pragma unroll
        for (int j = 0; j < 5; j++) acc[i][j] = 0.f;

    const float scale = 0.111803398875f;  // 1/sqrt(80)

    for (int k0 = 0; k0 < S_; k0 += 32) {
        for (int i = t; i < 32 * D_; i += 256) {
            int r = i / D_, c = i % D_;
            size_t off = hb + (size_t)(k0 + r) * D_ + c;
            Ks[r][c] = K[off];
            Vs[r][c] = V[off];
        }
        __syncthreads();

        float s00 = 0.f, s01 = 0.f, s10 = 0.f, s11 = 0.f;
        #pragma unroll 8
        for (int kk = 0; kk < D_; kk++) {
            float a0 = Qs[r0][kk], a1 = Qs[r1][kk];
            float b0 = Ks[c0][kk], b1 = Ks[c1][kk];
            s00 += a0 * b0; s01 += a0 * b1;
            s10 += a1 * b0; s11 += a1 * b1;
        }
        s00 *= scale; s01 *= scale; s10 *= scale; s11 *= scale;
        Ps[r0][c0] = s00; Ps[r0][c1] = s01;
        Ps[r1][c0] = s10; Ps[r1][c1] = s11;
        __syncthreads();

        if (t < 32) {
            float cm = -3.0e38f;
            #pragma unroll
            for (int j = 0; j < 32; j++) cm = fmaxf(cm, Ps[t][j]);
            float nm = fmaxf(mrow[t], cm);
            arow[t] = __expf(mrow[t] - nm);
            mrow[t] = nm;
        }
        __syncthreads();

        float m0v = mrow[r0], m1v = mrow[r1];
        float e00 = __expf(s00 - m0v), e01 = __expf(s01 - m0v);
        float e10 = __expf(s10 - m1v), e11 = __expf(s11 - m1v);
        Ps[r0][c0] = e00; Ps[r0][c1] = e01;
        Ps[r1][c0] = e10; Ps[r1][c1] = e11;
        __syncthreads();

        if (t < 32) {
            float sum = 0.f;
            #pragma unroll
            for (int j = 0; j < 32; j++) sum += Ps[t][j];
            lrow[t] = lrow[t] * arow[t] + sum;
        }
        float al0 = arow[r0], al1 = arow[r1];
        #pragma unroll
        for (int c = 0; c < 5; c++) { acc[0][c] *= al0; acc[1][c] *= al1; }
        #pragma unroll 4
        for (int j = 0; j < 32; j++) {
            float p0 = Ps[r0][j], p1 = Ps[r1][j];
            #pragma unroll
            for (int c = 0; c < 5; c++) {
                float vv = Vs[j][oc + c];
                acc[0][c] += p0 * vv;
                acc[1][c] += p1 * vv;
            }
        }
        __syncthreads();
    }

    float inv0 = 1.f / lrow[r0], inv1 = 1.f / lrow[r1];
    #pragma unroll
    for (int c = 0; c < 5; c++) {
        out[(size_t)(q0 + r0) * E_ + h * D_ + oc + c] = acc[0][c] * inv0;
        out[(size_t)(q0 + r1) * E_ + h * D_ + oc + c] = acc[1][c] * inv1;
    }
}

// ---------------- launch ----------------
extern "C" void kernel_launch(void* const* d_in, const int* in_sizes, int n_in,
                              void* d_out, int out_size) {
    const float* x    = (const float*)d_in[0];
    // d_in[1] = attention_mask (all true) — unused
    const float* cosp = (const float*)d_in[2];
    const float* sinp = (const float*)d_in[3];
    const float* ln1g = (const float*)d_in[4];
    const float* ln1b = (const float*)d_in[5];
    const float* ln2g = (const float*)d_in[6];
    const float* ln2b = (const float*)d_in[7];
    const float* wqkv = (const float*)d_in[8];
    const float* bqkv = (const float*)d_in[9];
    const float* wo   = (const float*)d_in[10];
    const float* bo   = (const float*)d_in[11];
    const float* wfc1 = (const float*)d_in[12];
    const float* bfc1 = (const float*)d_in[13];
    const float* wfc2 = (const float*)d_in[14];
    const float* bfc2 = (const float*)d_in[15];
    float* out = (float*)d_out;

    float *lnp, *qkvp, *qp, *kp, *vp, *attnp, *x1p, *ln2p, *fc1p;
    cudaGetSymbolAddress((void**)&lnp,   g_ln);
    cudaGetSymbolAddress((void**)&qkvp,  g_qkv);
    cudaGetSymbolAddress((void**)&qp,    g_q);
    cudaGetSymbolAddress((void**)&kp,    g_k);
    cudaGetSymbolAddress((void**)&vp,    g_v);
    cudaGetSymbolAddress((void**)&attnp, g_attn);
    cudaGetSymbolAddress((void**)&x1p,   g_x1);
    cudaGetSymbolAddress((void**)&ln2p,  g_ln2);
    cudaGetSymbolAddress((void**)&fc1p,  g_fc1);

    // 1. LN1
    ln_kernel<<<S_, 256>>>(x, ln1g, ln1b, lnp);
    // 2. QKV = ln1 @ w_qkv + b_qkv      [2048,1280]x[1280,3840]
    gemm_tf32<0><<<dim3(E3_ / 128, S_ / 128), 256>>>(lnp, wqkv, bqkv, nullptr, qkvp, S_, E3_, E_);
    // 3. RoPE + split into head-major q/k/v
    rope_kernel<<<(S_ * H_ * D_) / 256, 256>>>(qkvp, cosp, sinp, qp, kp, vp);
    // 4. Attention (flash, online softmax), writes [S, E] directly
    attn_kernel<<<dim3(S_ / 32, H_), 256>>>(qp, kp, vp, attnp);
    // 5. x1 = x + attn @ w_o + b_o
    gemm_tf32<2><<<dim3(E_ / 128, S_ / 128), 256>>>(attnp, wo, bo, x, x1p, S_, E_, E_);
    // 6. LN2
    ln_kernel<<<S_, 256>>>(x1p, ln2g, ln2b, ln2p);
    // 7. fc1 = quickgelu(ln2 @ w_fc1 + b_fc1)    [2048,1280]x[1280,5120]
    gemm_tf32<1><<<dim3(F_ / 128, S_ / 128), 256>>>(ln2p, wfc1, bfc1, nullptr, fc1p, S_, F_, E_);
    // 8. out = x1 + fc1 @ w_fc2 + b_fc2          [2048,5120]x[5120,1280]
    gemm_tf32<2><<<dim3(E_ / 128, S_ / 128), 256>>>(fc1p, wfc2, bfc2, x1p, out, S_, E_, F_);
}

// round 11
// speedup vs baseline: 1.0012x; 1.0012x over previous
#include <cuda_runtime.h>
#include <stdint.h>
#include <math.h>

#define S_ 2048
#define E_ 1280
#define H_ 16
#define D_ 80
#define F_ 5120
#define E3_ 3840

// ---------------- scratch (device globals; no runtime allocation) ----------------
__device__ float g_ln[S_ * E_];
__device__ float g_qkv[S_ * E3_];
__device__ float g_q[H_ * S_ * D_];
__device__ float g_k[H_ * S_ * D_];
__device__ float g_v[H_ * S_ * D_];
__device__ float g_attn[S_ * E_];
__device__ float g_x1[S_ * E_];
__device__ float g_ln2[S_ * E_];
__device__ float g_fc1[S_ * F_];

// ---------------- helpers ----------------
__device__ __forceinline__ uint32_t f2tf(float x) {
    uint32_t r;
    asm("cvt.rna.tf32.f32 %0, %1;" : "=r"(r) : "f"(x));
    return r;
}

__device__ __forceinline__ void mma_tf32(float* c, const uint32_t* a, uint32_t b0, uint32_t b1) {
    asm volatile(
        "mma.sync.aligned.m16n8k8.row.col.f32.tf32.tf32.f32 "
        "{%0,%1,%2,%3}, {%4,%5,%6,%7}, {%8,%9}, {%0,%1,%2,%3};\n"
        : "+f"(c[0]), "+f"(c[1]), "+f"(c[2]), "+f"(c[3])
        : "r"(a[0]), "r"(a[1]), "r"(a[2]), "r"(a[3]), "r"(b0), "r"(b1));
}

// ---------------- LayerNorm ----------------
__global__ __launch_bounds__(256) void ln_kernel(const float* __restrict__ x,
                                                 const float* __restrict__ g,
                                                 const float* __restrict__ b,
                                                 float* __restrict__ out) {
    int row = blockIdx.x;
    const float* xr = x + (size_t)row * E_;
    float s = 0.f, s2 = 0.f;
    for (int i = threadIdx.x; i < E_; i += 256) {
        float v = xr[i];
        s += v; s2 += v * v;
    }
    __shared__ float sh[32];
    #pragma unroll
    for (int o = 16; o > 0; o >>= 1) {
        s  += __shfl_down_sync(0xffffffffu, s, o);
        s2 += __shfl_down_sync(0xffffffffu, s2, o);
    }
    int w = threadIdx.x >> 5, l = threadIdx.x & 31;
    if (l == 0) { sh[w] = s; sh[w + 8] = s2; }
    __syncthreads();
    if (threadIdx.x == 0) {
        float ts = 0.f, ts2 = 0.f;
        #pragma unroll
        for (int i = 0; i < 8; i++) { ts += sh[i]; ts2 += sh[i + 8]; }
        float mean = ts / E_;
        float var = ts2 / E_ - mean * mean;
        sh[16] = mean;
        sh[17] = rsqrtf(var + 1e-6f);
    }
    __syncthreads();
    float mean = sh[16], inv = sh[17];
    for (int i = threadIdx.x; i < E_; i += 256) {
        out[(size_t)row * E_ + i] = (xr[i] - mean) * inv * g[i] + b[i];
    }
}

// ---------------- tf32 tensor-core GEMM ----------------
// C[M,N] = A[M,K] @ B[K,N] + bias (+epilogue)
// MODE 0: bias only.  MODE 1: bias + quickGELU.  MODE 2: bias + residual R.
// 128x128 block tile, k-tile 16, double-buffered smem, 256 threads.
// Warp (wm,wn) owns 32x64: 2 m-tiles (m16) x 8 n-tiles (n8), mma.m16n8k8.tf32.
#define AS_STRIDE 20
#define BS_STRIDE 136
template <int MODE>
__global__ __launch_bounds__(256) void gemm_tf32(const float* __restrict__ A,
                                                 const float* __restrict__ B,
                                                 const float* __restrict__ bias,
                                                 const float* __restrict__ R,
                                                 float* __restrict__ C,
                                                 int M, int N, int K) {
    __shared__ uint32_t As[2][128 * AS_STRIDE];
    __shared__ uint32_t Bs[2][16 * BS_STRIDE];

    const int t = threadIdx.x;
    const int warp = t >> 5, lane = t & 31;
    const int g = lane >> 2, tg = lane & 3;
    const int wm = warp >> 1, wn = warp & 1;
    const int m0 = blockIdx.y * 128, n0 = blockIdx.x * 128;

    float acc[2][8][4];
    #pragma unroll
    for (int mt = 0; mt < 2; mt++)
        #pragma unroll
        for (int nt = 0; nt < 8; nt++)
            #pragma unroll
            for (int r = 0; r < 4; r++) acc[mt][nt][r] = 0.f;

    const float* Ap = A + (size_t)m0 * K;
    const float* Bp = B + n0;

    float4 ra[2], rb[2];

    // ---- LDG tile k0 ----
    #define LDG_TILE(k0)                                                              \
        {                                                                             \
            _Pragma("unroll")                                                         \
            for (int i = 0; i < 2; i++) {                                             \
                int idx = t + 256 * i;                                                \
                ra[i] = *(const float4*)(Ap + (size_t)(idx >> 2) * K + (k0) + (idx & 3) * 4); \
                rb[i] = *(const float4*)(Bp + (size_t)((k0) + (idx >> 5)) * N + (idx & 31) * 4); \
            }                                                                         \
        }

    // ---- STS to buffer ----
    #define STS_TILE(buf)                                                             \
        {                                                                             \
            _Pragma("unroll")                                                         \
            for (int i = 0; i < 2; i++) {                                             \
                int idx = t + 256 * i;                                                \
                uint4 va = make_uint4(f2tf(ra[i].x), f2tf(ra[i].y), f2tf(ra[i].z), f2tf(ra[i].w)); \
                *(uint4*)&As[buf][(idx >> 2) * AS_STRIDE + (idx & 3) * 4] = va;       \
                uint4 vb = make_uint4(f2tf(rb[i].x), f2tf(rb[i].y), f2tf(rb[i].z), f2tf(rb[i].w)); \
                *(uint4*)&Bs[buf][(idx >> 5) * BS_STRIDE + (idx & 31) * 4] = vb;      \
            }                                                                         \
        }

    const int NK = K / 16;
    LDG_TILE(0);
    STS_TILE(0);
    __syncthreads();

    for (int it = 0; it < NK; it++) {
        if (it + 1 < NK) LDG_TILE((it + 1) * 16);
        const int buf = it & 1;
        #pragma unroll
        for (int ks = 0; ks < 2; ks++) {
            uint32_t af[2][4];
            #pragma unroll
            for (int mt = 0; mt < 2; mt++) {
                const uint32_t* ab = &As[buf][(wm * 32 + mt * 16 + g) * AS_STRIDE + ks * 8 + tg];
                af[mt][0] = ab[0];
                af[mt][1] = ab[8 * AS_STRIDE];
                af[mt][2] = ab[4];
                af[mt][3] = ab[8 * AS_STRIDE + 4];
            }
            #pragma unroll
            for (int nt = 0; nt < 8; nt++) {
                const uint32_t* bb = &Bs[buf][(ks * 8 + tg) * BS_STRIDE + wn * 64 + nt * 8 + g];
                uint32_t b0 = bb[0];
                uint32_t b1 = bb[4 * BS_STRIDE];
                #pragma unroll
                for (int mt = 0; mt < 2; mt++) mma_tf32(acc[mt][nt], af[mt], b0, b1);
            }
        }
        if (it + 1 < NK) {
            STS_TILE((it + 1) & 1);
            __syncthreads();
        }
    }

    // ---- epilogue ----
    #pragma unroll
    for (int mt = 0; mt < 2; mt++) {
        int r0 = m0 + wm * 32 + mt * 16 + g;
        int r1 = r0 + 8;
        #pragma unroll
        for (int nt = 0; nt < 8; nt++) {
            int col = n0 + wn * 64 + nt * 8 + tg * 2;
            float b0 = bias[col], b1 = bias[col + 1];
            float v0 = acc[mt][nt][0] + b0;
            float v1 = acc[mt][nt][1] + b1;
            float v2 = acc[mt][nt][2] + b0;
            float v3 = acc[mt][nt][3] + b1;
            if (MODE == 1) {
                v0 = v0 / (1.f + __expf(-1.702f * v0));
                v1 = v1 / (1.f + __expf(-1.702f * v1));
                v2 = v2 / (1.f + __expf(-1.702f * v2));
                v3 = v3 / (1.f + __expf(-1.702f * v3));
            }
            if (MODE == 2) {
                float2 rr0 = *(const float2*)&R[(size_t)r0 * N + col];
                float2 rr1 = *(const float2*)&R[(size_t)r1 * N + col];
                v0 += rr0.x; v1 += rr0.y; v2 += rr1.x; v3 += rr1.y;
            }
            *(float2*)&C[(size_t)r0 * N + col] = make_float2(v0, v1);
            *(float2*)&C[(size_t)r1 * N + col] = make_float2(v2, v3);
        }
    }
}

// ---------------- RoPE + head split (q,k rotated; v copied) ----------------
__global__ __launch_bounds__(256) void rope_kernel(const float* __restrict__ qkv,
                                                   const float* __restrict__ cosp,
                                                   const float* __restrict__ sinp,
                                                   float* __restrict__ q,
                                                   float* __restrict__ k,
                                                   float* __restrict__ v) {
    int idx = blockIdx.x * 256 + threadIdx.x;
    if (idx >= S_ * H_ * D_) return;
    int d = idx % D_;
    int h = (idx / D_) % H_;
    int s = idx / (H_ * D_);
    float c = cosp[s * D_ + d], sn = sinp[s * D_ + d];
    size_t base = (size_t)s * E3_ + h * D_;
    float qv = qkv[base + d];
    float kv = qkv[base + E_ + d];
    float vv = qkv[base + 2 * E_ + d];
    int dro = (d < 40) ? d + 40 : d - 40;
    float sgn = (d < 40) ? -1.f : 1.f;
    float qr = sgn * qkv[base + dro];
    float kr = sgn * qkv[base + E_ + dro];
    size_t o = ((size_t)h * S_ + s) * D_ + d;
    q[o] = qv * c + qr * sn;
    k[o] = kv * c + kr * sn;
    v[o] = vv;
}

// ---------------- Flash attention (fp32, online softmax) ----------------
__global__ __launch_bounds__(256) void attn_kernel(const float* __restrict__ Q,
                                                   const float* __restrict__ K,
                                                   const float* __restrict__ V,
                                                   float* __restrict__ out) {
    __shared__ float Qs[32][81];
    __shared__ float Ks[32][81];
    __shared__ float Vs[32][81];
    __shared__ float Ps[32][33];
    __shared__ float mrow[32], lrow[32], arow[32];

    int h = blockIdx.y;
    int q0 = blockIdx.x * 32;
    int t = threadIdx.x;
    int ty = t >> 4, tx = t & 15;
    int r0 = ty * 2, r1 = r0 + 1;
    int c0 = tx * 2, c1 = c0 + 1;
    int oc = tx * 5;
    const size_t hb = (size_t)h * S_ * D_;

    for (int i = t; i < 32 * D_; i += 256) {
        int r = i / D_, c = i % D_;
        Qs[r][c] = Q[hb + (size_t)(q0 + r) * D_ + c];
    }
    if (t < 32) { mrow[t] = -3.0e38f; lrow[t] = 0.f; }
    float acc[2][5];
    #pragma unroll
    for (int i = 0; i < 2; i++)
        #pragma unroll
        for (int j = 0; j < 5; j++) acc[i][j] = 0.f;

    const float scale = 0.111803398875f;  // 1/sqrt(80)

    for (int k0 = 0; k0 < S_; k0 += 32) {
        for (int i = t; i < 32 * D_; i += 256) {
            int r = i / D_, c = i % D_;
            size_t off = hb + (size_t)(k0 + r) * D_ + c;
            Ks[r][c] = K[off];
            Vs[r][c] = V[off];
        }
        __syncthreads();

        float s00 = 0.f, s01 = 0.f, s10 = 0.f, s11 = 0.f;
        #pragma unroll 8
        for (int kk = 0; kk < D_; kk++) {
            float a0 = Qs[r0][kk], a1 = Qs[r1][kk];
            float b0 = Ks[c0][kk], b1 = Ks[c1][kk];
            s00 += a0 * b0; s01 += a0 * b1;
            s10 += a1 * b0; s11 += a1 * b1;
        }
        s00 *= scale; s01 *= scale; s10 *= scale; s11 *= scale;
        Ps[r0][c0] = s00; Ps[r0][c1] = s01;
        Ps[r1][c0] = s10; Ps[r1][c1] = s11;
        __syncthreads();

        if (t < 32) {
            float cm = -3.0e38f;
            #pragma unroll
            for (int j = 0; j < 32; j++) cm = fmaxf(cm, Ps[t][j]);
            float nm = fmaxf(mrow[t], cm);
            arow[t] = __expf(mrow[t] - nm);
            mrow[t] = nm;
        }
        __syncthreads();

        float m0v = mrow[r0], m1v = mrow[r1];
        float e00 = __expf(s00 - m0v), e01 = __expf(s01 - m0v);
        float e10 = __expf(s10 - m1v), e11 = __expf(s11 - m1v);
        Ps[r0][c0] = e00; Ps[r0][c1] = e01;
        Ps[r1][c0] = e10; Ps[r1][c1] = e11;
        __syncthreads();

        if (t < 32) {
            float sum = 0.f;
            #pragma unroll
            for (int j = 0; j < 32; j++) sum += Ps[t][j];
            lrow[t] = lrow[t] * arow[t] + sum;
        }
        float al0 = arow[r0], al1 = arow[r1];
        #pragma unroll
        for (int c = 0; c < 5; c++) { acc[0][c] *= al0; acc[1][c] *= al1; }
        #pragma unroll 4
        for (int j = 0; j < 32; j++) {
            float p0 = Ps[r0][j], p1 = Ps[r1][j];
            #pragma unroll
            for (int c = 0; c < 5; c++) {
                float vv = Vs[j][oc + c];
                acc[0][c] += p0 * vv;
                acc[1][c] += p1 * vv;
            }
        }
        __syncthreads();
    }

    float inv0 = 1.f / lrow[r0], inv1 = 1.f / lrow[r1];
    #pragma unroll
    for (int c = 0; c < 5; c++) {
        out[(size_t)(q0 + r0) * E_ + h * D_ + oc + c] = acc[0][c] * inv0;
        out[(size_t)(q0 + r1) * E_ + h * D_ + oc + c] = acc[1][c] * inv1;
    }
}

// ---------------- launch ----------------
extern "C" void kernel_launch(void* const* d_in, const int* in_sizes, int n_in,
                              void* d_out, int out_size) {
    const float* x    = (const float*)d_in[0];
    // d_in[1] = attention_mask (all true) — unused
    const float* cosp = (const float*)d_in[2];
    const float* sinp = (const float*)d_in[3];
    const float* ln1g = (const float*)d_in[4];
    const float* ln1b = (const float*)d_in[5];
    const float* ln2g = (const float*)d_in[6];
    const float* ln2b = (const float*)d_in[7];
    const float* wqkv = (const float*)d_in[8];
    const float* bqkv = (const float*)d_in[9];
    const float* wo   = (const float*)d_in[10];
    const float* bo   = (const float*)d_in[11];
    const float* wfc1 = (const float*)d_in[12];
    const float* bfc1 = (const float*)d_in[13];
    const float* wfc2 = (const float*)d_in[14];
    const float* bfc2 = (const float*)d_in[15];
    float* out = (float*)d_out;

    float *lnp, *qkvp, *qp, *kp, *vp, *attnp, *x1p, *ln2p, *fc1p;
    cudaGetSymbolAddress((void**)&lnp,   g_ln);
    cudaGetSymbolAddress((void**)&qkvp,  g_qkv);
    cudaGetSymbolAddress((void**)&qp,    g_q);
    cudaGetSymbolAddress((void**)&kp,    g_k);
    cudaGetSymbolAddress((void**)&vp,    g_v);
    cudaGetSymbolAddress((void**)&attnp, g_attn);
    cudaGetSymbolAddress((void**)&x1p,   g_x1);
    cudaGetSymbolAddress((void**)&ln2p,  g_ln2);
    cudaGetSymbolAddress((void**)&fc1p,  g_fc1);

    // 1. LN1
    ln_kernel<<<S_, 256>>>(x, ln1g, ln1b, lnp);
    // 2. QKV = ln1 @ w_qkv + b_qkv      [2048,1280]x[1280,3840]
    gemm_tf32<0><<<dim3(E3_ / 128, S_ / 128), 256>>>(lnp, wqkv, bqkv, nullptr, qkvp, S_, E3_, E_);
    // 3. RoPE + split into head-major q/k/v
    rope_kernel<<<(S_ * H_ * D_) / 256, 256>>>(qkvp, cosp, sinp, qp, kp, vp);
    // 4. Attention (flash, online softmax), writes [S, E] directly
    attn_kernel<<<dim3(S_ / 32, H_), 256>>>(qp, kp, vp, attnp);
    // 5. x1 = x + attn @ w_o + b_o
    gemm_tf32<2><<<dim3(E_ / 128, S_ / 128), 256>>>(attnp, wo, bo, x, x1p, S_, E_, E_);
    // 6. LN2
    ln_kernel<<<S_, 256>>>(x1p, ln2g, ln2b, ln2p);
    // 7. fc1 = quickgelu(ln2 @ w_fc1 + b_fc1)    [2048,1280]x[1280,5120]
    gemm_tf32<1><<<dim3(F_ / 128, S_ / 128), 256>>>(ln2p, wfc1, bfc1, nullptr, fc1p, S_, F_, E_);
    // 8. out = x1 + fc1 @ w_fc2 + b_fc2          [2048,5120]x[5120,1280]
    gemm_tf32<2><<<dim3(E_ / 128, S_ / 128), 256>>>(fc1p, wfc2, bfc2, x1p, out, S_, E_, F_);
}

// round 12
// speedup vs baseline: 1.0021x; 1.0009x over previous
#include <cuda_runtime.h>
#include <stdint.h>
#include <math.h>

#define S_ 2048
#define E_ 1280
#define H_ 16
#define D_ 80
#define F_ 5120
#define E3_ 3840

// ---------------- scratch (device globals; no runtime allocation) ----------------
__device__ float g_ln[S_ * E_];
__device__ float g_qkv[S_ * E3_];
__device__ float g_q[H_ * S_ * D_];
__device__ float g_k[H_ * S_ * D_];
__device__ float g_v[H_ * S_ * D_];
__device__ float g_attn[S_ * E_];
__device__ float g_x1[S_ * E_];
__device__ float g_ln2[S_ * E_];
__device__ float g_fc1[S_ * F_];

// ---------------- helpers ----------------
__device__ __forceinline__ uint32_t f2tf(float x) {
    uint32_t r;
    asm("cvt.rna.tf32.f32 %0, %1;" : "=r"(r) : "f"(x));
    return r;
}

__device__ __forceinline__ void mma_tf32(float* c, const uint32_t* a, uint32_t b0, uint32_t b1) {
    asm volatile(
        "mma.sync.aligned.m16n8k8.row.col.f32.tf32.tf32.f32 "
        "{%0,%1,%2,%3}, {%4,%5,%6,%7}, {%8,%9}, {%0,%1,%2,%3};\n"
        : "+f"(c[0]), "+f"(c[1]), "+f"(c[2]), "+f"(c[3])
        : "r"(a[0]), "r"(a[1]), "r"(a[2]), "r"(a[3]), "r"(b0), "r"(b1));
}

// ---------------- LayerNorm ----------------
__global__ __launch_bounds__(256) void ln_kernel(const float* __restrict__ x,
                                                 const float* __restrict__ g,
                                                 const float* __restrict__ b,
                                                 float* __restrict__ out) {
    int row = blockIdx.x;
    const float* xr = x + (size_t)row * E_;
    float s = 0.f, s2 = 0.f;
    for (int i = threadIdx.x; i < E_; i += 256) {
        float v = xr[i];
        s += v; s2 += v * v;
    }
    __shared__ float sh[32];
    #pragma unroll
    for (int o = 16; o > 0; o >>= 1) {
        s  += __shfl_down_sync(0xffffffffu, s, o);
        s2 += __shfl_down_sync(0xffffffffu, s2, o);
    }
    int w = threadIdx.x >> 5, l = threadIdx.x & 31;
    if (l == 0) { sh[w] = s; sh[w + 8] = s2; }
    __syncthreads();
    if (threadIdx.x == 0) {
        float ts = 0.f, ts2 = 0.f;
        #pragma unroll
        for (int i = 0; i < 8; i++) { ts += sh[i]; ts2 += sh[i + 8]; }
        float mean = ts / E_;
        float var = ts2 / E_ - mean * mean;
        sh[16] = mean;
        sh[17] = rsqrtf(var + 1e-6f);
    }
    __syncthreads();
    float mean = sh[16], inv = sh[17];
    for (int i = threadIdx.x; i < E_; i += 256) {
        out[(size_t)row * E_ + i] = (xr[i] - mean) * inv * g[i] + b[i];
    }
}

// ---------------- tf32 tensor-core GEMM ----------------
// C[M,N] = A[M,K] @ B[K,N] + bias (+epilogue)
// MODE 0: bias only.  MODE 1: bias + quickGELU.  MODE 2: bias + residual R.
// 128x128 block tile, k-tile 16, double-buffered smem, 256 threads.
// Warp (wm,wn) owns 32x64: 2 m-tiles (m16) x 8 n-tiles (n8), mma.m16n8k8.tf32.
#define AS_STRIDE 20
#define BS_STRIDE 136
template <int MODE>
__global__ __launch_bounds__(256) void gemm_tf32(const float* __restrict__ A,
                                                 const float* __restrict__ B,
                                                 const float* __restrict__ bias,
                                                 const float* __restrict__ R,
                                                 float* __restrict__ C,
                                                 int M, int N, int K) {
    __shared__ uint32_t As[2][128 * AS_STRIDE];
    __shared__ uint32_t Bs[2][16 * BS_STRIDE];

    const int t = threadIdx.x;
    const int warp = t >> 5, lane = t & 31;
    const int g = lane >> 2, tg = lane & 3;
    const int wm = warp >> 1, wn = warp & 1;
    const int m0 = blockIdx.y * 128, n0 = blockIdx.x * 128;

    float acc[2][8][4];
    #pragma unroll
    for (int mt = 0; mt < 2; mt++)
        #pragma unroll
        for (int nt = 0; nt < 8; nt++)
            #pragma unroll
            for (int r = 0; r < 4; r++) acc[mt][nt][r] = 0.f;

    const float* Ap = A + (size_t)m0 * K;
    const float* Bp = B + n0;

    float4 ra[2], rb[2];

    // ---- LDG tile k0 ----
    #define LDG_TILE(k0)                                                              \
        {                                                                             \
            _Pragma("unroll")                                                         \
            for (int i = 0; i < 2; i++) {                                             \
                int idx = t + 256 * i;                                                \
                ra[i] = *(const float4*)(Ap + (size_t)(idx >> 2) * K + (k0) + (idx & 3) * 4); \
                rb[i] = *(const float4*)(Bp + (size_t)((k0) + (idx >> 5)) * N + (idx & 31) * 4); \
            }                                                                         \
        }

    // ---- STS to buffer ----
    #define STS_TILE(buf)                                                             \
        {                                                                             \
            _Pragma("unroll")                                                         \
            for (int i = 0; i < 2; i++) {                                             \
                int idx = t + 256 * i;                                                \
                uint4 va = make_uint4(f2tf(ra[i].x), f2tf(ra[i].y), f2tf(ra[i].z), f2tf(ra[i].w)); \
                *(uint4*)&As[buf][(idx >> 2) * AS_STRIDE + (idx & 3) * 4] = va;       \
                uint4 vb = make_uint4(f2tf(rb[i].x), f2tf(rb[i].y), f2tf(rb[i].z), f2tf(rb[i].w)); \
                *(uint4*)&Bs[buf][(idx >> 5) * BS_STRIDE + (idx & 31) * 4] = vb;      \
            }                                                                         \
        }

    const int NK = K / 16;
    LDG_TILE(0);
    STS_TILE(0);
    __syncthreads();

    for (int it = 0; it < NK; it++) {
        if (it + 1 < NK) LDG_TILE((it + 1) * 16);
        const int buf = it & 1;
        #pragma unroll
        for (int ks = 0; ks < 2; ks++) {
            uint32_t af[2][4];
            #pragma unroll
            for (int mt = 0; mt < 2; mt++) {
                const uint32_t* ab = &As[buf][(wm * 32 + mt * 16 + g) * AS_STRIDE + ks * 8 + tg];
                af[mt][0] = ab[0];
                af[mt][1] = ab[8 * AS_STRIDE];
                af[mt][2] = ab[4];
                af[mt][3] = ab[8 * AS_STRIDE + 4];
            }
            #pragma unroll
            for (int nt = 0; nt < 8; nt++) {
                const uint32_t* bb = &Bs[buf][(ks * 8 + tg) * BS_STRIDE + wn * 64 + nt * 8 + g];
                uint32_t b0 = bb[0];
                uint32_t b1 = bb[4 * BS_STRIDE];
                #pragma unroll
                for (int mt = 0; mt < 2; mt++) mma_tf32(acc[mt][nt], af[mt], b0, b1);
            }
        }
        if (it + 1 < NK) {
            STS_TILE((it + 1) & 1);
            __syncthreads();
        }
    }

    // ---- epilogue ----
    #pragma unroll
    for (int mt = 0; mt < 2; mt++) {
        int r0 = m0 + wm * 32 + mt * 16 + g;
        int r1 = r0 + 8;
        #pragma unroll
        for (int nt = 0; nt < 8; nt++) {
            int col = n0 + wn * 64 + nt * 8 + tg * 2;
            float b0 = bias[col], b1 = bias[col + 1];
            float v0 = acc[mt][nt][0] + b0;
            float v1 = acc[mt][nt][1] + b1;
            float v2 = acc[mt][nt][2] + b0;
            float v3 = acc[mt][nt][3] + b1;
            if (MODE == 1) {
                v0 = v0 / (1.f + __expf(-1.702f * v0));
                v1 = v1 / (1.f + __expf(-1.702f * v1));
                v2 = v2 / (1.f + __expf(-1.702f * v2));
                v3 = v3 / (1.f + __expf(-1.702f * v3));
            }
            if (MODE == 2) {
                float2 rr0 = *(const float2*)&R[(size_t)r0 * N + col];
                float2 rr1 = *(const float2*)&R[(size_t)r1 * N + col];
                v0 += rr0.x; v1 += rr0.y; v2 += rr1.x; v3 += rr1.y;
            }
            *(float2*)&C[(size_t)r0 * N + col] = make_float2(v0, v1);
            *(float2*)&C[(size_t)r1 * N + col] = make_float2(v2, v3);
        }
    }
}

// ---------------- RoPE + head split (q,k rotated; v copied) ----------------
__global__ __launch_bounds__(256) void rope_kernel(const float* __restrict__ qkv,
                                                   const float* __restrict__ cosp,
                                                   const float* __restrict__ sinp,
                                                   float* __restrict__ q,
                                                   float* __restrict__ k,
                                                   float* __restrict__ v) {
    int idx = blockIdx.x * 256 + threadIdx.x;
    if (idx >= S_ * H_ * D_) return;
    int d = idx % D_;
    int h = (idx / D_) % H_;
    int s = idx / (H_ * D_);
    float c = cosp[s * D_ + d], sn = sinp[s * D_ + d];
    size_t base = (size_t)s * E3_ + h * D_;
    float qv = qkv[base + d];
    float kv = qkv[base + E_ + d];
    float vv = qkv[base + 2 * E_ + d];
    int dro = (d < 40) ? d + 40 : d - 40;
    float sgn = (d < 40) ? -1.f : 1.f;
    float qr = sgn * qkv[base + dro];
    float kr = sgn * qkv[base + E_ + dro];
    size_t o = ((size_t)h * S_ + s) * D_ + d;
    q[o] = qv * c + qr * sn;
    k[o] = kv * c + kr * sn;
    v[o] = vv;
}

// ---------------- Flash attention (fp32, online softmax) ----------------
__global__ __launch_bounds__(256) void attn_kernel(const float* __restrict__ Q,
                                                   const float* __restrict__ K,
                                                   const float* __restrict__ V,
                                                   float* __restrict__ out) {
    __shared__ float Qs[32][81];
    __shared__ float Ks[32][81];
    __shared__ float Vs[32][81];
    __shared__ float Ps[32][33];
    __shared__ float mrow[32], lrow[32], arow[32];

    int h = blockIdx.y;
    int q0 = blockIdx.x * 32;
    int t = threadIdx.x;
    int ty = t >> 4, tx = t & 15;
    int r0 = ty * 2, r1 = r0 + 1;
    int c0 = tx * 2, c1 = c0 + 1;
    int oc = tx * 5;
    const size_t hb = (size_t)h * S_ * D_;

    for (int i = t; i < 32 * D_; i += 256) {
        int r = i / D_, c = i % D_;
        Qs[r][c] = Q[hb + (size_t)(q0 + r) * D_ + c];
    }
    if (t < 32) { mrow[t] = -3.0e38f; lrow[t] = 0.f; }
    float acc[2][5];
    #pragma unroll
    for (int i = 0; i < 2; i++)
        #pragma unroll
        for (int j = 0; j < 5; j++) acc[i][j] = 0.f;

    const float scale = 0.111803398875f;  // 1/sqrt(80)

    for (int k0 = 0; k0 < S_; k0 += 32) {
        for (int i = t; i < 32 * D_; i += 256) {
            int r = i / D_, c = i % D_;
            size_t off = hb + (size_t)(k0 + r) * D_ + c;
            Ks[r][c] = K[off];
            Vs[r][c] = V[off];
        }
        __syncthreads();

        float s00 = 0.f, s01 = 0.f, s10 = 0.f, s11 = 0.f;
        #pragma unroll 8
        for (int kk = 0; kk < D_; kk++) {
            float a0 = Qs[r0][kk], a1 = Qs[r1][kk];
            float b0 = Ks[c0][kk], b1 = Ks[c1][kk];
            s00 += a0 * b0; s01 += a0 * b1;
            s10 += a1 * b0; s11 += a1 * b1;
        }
        s00 *= scale; s01 *= scale; s10 *= scale; s11 *= scale;
        Ps[r0][c0] = s00; Ps[r0][c1] = s01;
        Ps[r1][c0] = s10; Ps[r1][c1] = s11;
        __syncthreads();

        if (t < 32) {
            float cm = -3.0e38f;
            #pragma unroll
            for (int j = 0; j < 32; j++) cm = fmaxf(cm, Ps[t][j]);
            float nm = fmaxf(mrow[t], cm);
            arow[t] = __expf(mrow[t] - nm);
            mrow[t] = nm;
        }
        __syncthreads();

        float m0v = mrow[r0], m1v = mrow[r1];
        float e00 = __expf(s00 - m0v), e01 = __expf(s01 - m0v);
        float e10 = __expf(s10 - m1v), e11 = __expf(s11 - m1v);
        Ps[r0][c0] = e00; Ps[r0][c1] = e01;
        Ps[r1][c0] = e10; Ps[r1][c1] = e11;
        __syncthreads();

        if (t < 32) {
            float sum = 0.f;
            #pragma unroll
            for (int j = 0; j < 32; j++) sum += Ps[t][j];
            lrow[t] = lrow[t] * arow[t] + sum;
        }
        float al0 = arow[r0], al1 = arow[r1];
        #pragma unroll
        for (int c = 0; c < 5; c++) { acc[0][c] *= al0; acc[1][c] *= al1; }
        #pragma unroll 4
        for (int j = 0; j < 32; j++) {
            float p0 = Ps[r0][j], p1 = Ps[r1][j];
            #pragma unroll
            for (int c = 0; c < 5; c++) {
                float vv = Vs[j][oc + c];
                acc[0][c] += p0 * vv;
                acc[1][c] += p1 * vv;
            }
        }
        __syncthreads();
    }

    float inv0 = 1.f / lrow[r0], inv1 = 1.f / lrow[r1];
    #pragma unroll
    for (int c = 0; c < 5; c++) {
        out[(size_t)(q0 + r0) * E_ + h * D_ + oc + c] = acc[0][c] * inv0;
        out[(size_t)(q0 + r1) * E_ + h * D_ + oc + c] = acc[1][c] * inv1;
    }
}

// ---------------- launch ----------------
extern "C" void kernel_launch(void* const* d_in, const int* in_sizes, int n_in,
                              void* d_out, int out_size) {
    const float* x    = (const float*)d_in[0];
    // d_in[1] = attention_mask (all true) — unused
    const float* cosp = (const float*)d_in[2];
    const float* sinp = (const float*)d_in[3];
    const float* ln1g = (const float*)d_in[4];
    const float* ln1b = (const float*)d_in[5];
    const float* ln2g = (const float*)d_in[6];
    const float* ln2b = (const float*)d_in[7];
    const float* wqkv = (const float*)d_in[8];
    const float* bqkv = (const float*)d_in[9];
    const float* wo   = (const float*)d_in[10];
    const float* bo   = (const float*)d_in[11];
    const float* wfc1 = (const float*)d_in[12];
    const float* bfc1 = (const float*)d_in[13];
    const float* wfc2 = (const float*)d_in[14];
    const float* bfc2 = (const float*)d_in[15];
    float* out = (float*)d_out;

    float *lnp, *qkvp, *qp, *kp, *vp, *attnp, *x1p, *ln2p, *fc1p;
    cudaGetSymbolAddress((void**)&lnp,   g_ln);
    cudaGetSymbolAddress((void**)&qkvp,  g_qkv);
    cudaGetSymbolAddress((void**)&qp,    g_q);
    cudaGetSymbolAddress((void**)&kp,    g_k);
    cudaGetSymbolAddress((void**)&vp,    g_v);
    cudaGetSymbolAddress((void**)&attnp, g_attn);
    cudaGetSymbolAddress((void**)&x1p,   g_x1);
    cudaGetSymbolAddress((void**)&ln2p,  g_ln2);
    cudaGetSymbolAddress((void**)&fc1p,  g_fc1);

    // 1. LN1
    ln_kernel<<<S_, 256>>>(x, ln1g, ln1b, lnp);
    // 2. QKV = ln1 @ w_qkv + b_qkv      [2048,1280]x[1280,3840]
    gemm_tf32<0><<<dim3(E3_ / 128, S_ / 128), 256>>>(lnp, wqkv, bqkv, nullptr, qkvp, S_, E3_, E_);
    // 3. RoPE + split into head-major q/k/v
    rope_kernel<<<(S_ * H_ * D_) / 256, 256>>>(qkvp, cosp, sinp, qp, kp, vp);
    // 4. Attention (flash, online softmax), writes [S, E] directly
    attn_kernel<<<dim3(S_ / 32, H_), 256>>>(qp, kp, vp, attnp);
    // 5. x1 = x + attn @ w_o + b_o
    gemm_tf32<2><<<dim3(E_ / 128, S_ / 128), 256>>>(attnp, wo, bo, x, x1p, S_, E_, E_);
    // 6. LN2
    ln_kernel<<<S_, 256>>>(x1p, ln2g, ln2b, ln2p);
    // 7. fc1 = quickgelu(ln2 @ w_fc1 + b_fc1)    [2048,1280]x[1280,5120]
    gemm_tf32<1><<<dim3(F_ / 128, S_ / 128), 256>>>(ln2p, wfc1, bfc1, nullptr, fc1p, S_, F_, E_);
    // 8. out = x1 + fc1 @ w_fc2 + b_fc2          [2048,5120]x[5120,1280]
    gemm_tf32<2><<<dim3(E_ / 128, S_ / 128), 256>>>(fc1p, wfc2, bfc2, x1p, out, S_, E_, F_);
}

// round 13
// speedup vs baseline: 1.6304x; 1.6269x over previous
#include <cuda_runtime.h>
#include <stdint.h>
#include <math.h>

#define S_ 2048
#define E_ 1280
#define H_ 16
#define D_ 80
#define F_ 5120
#define E3_ 3840

// ---------------- scratch (device globals; no runtime allocation) ----------------
__device__ float g_ln[S_ * E_];
__device__ float g_qkv[S_ * E3_];
__device__ float g_q[H_ * S_ * D_];
__device__ float g_k[H_ * S_ * D_];
__device__ float g_v[H_ * S_ * D_];
__device__ float g_attn[S_ * E_];
__device__ float g_x1[S_ * E_];
__device__ float g_ln2[S_ * E_];
__device__ float g_fc1[S_ * F_];

// ---------------- helpers ----------------
__device__ __forceinline__ uint32_t f2tf(float x) {
    uint32_t r;
    asm("cvt.rna.tf32.f32 %0, %1;" : "=r"(r) : "f"(x));
    return r;
}

__device__ __forceinline__ void mma_tf32(float* c, const uint32_t* a, uint32_t b0, uint32_t b1) {
    asm volatile(
        "mma.sync.aligned.m16n8k8.row.col.f32.tf32.tf32.f32 "
        "{%0,%1,%2,%3}, {%4,%5,%6,%7}, {%8,%9}, {%0,%1,%2,%3};\n"
        : "+f"(c[0]), "+f"(c[1]), "+f"(c[2]), "+f"(c[3])
        : "r"(a[0]), "r"(a[1]), "r"(a[2]), "r"(a[3]), "r"(b0), "r"(b1));
}

// ---------------- LayerNorm ----------------
__global__ __launch_bounds__(256) void ln_kernel(const float* __restrict__ x,
                                                 const float* __restrict__ g,
                                                 const float* __restrict__ b,
                                                 float* __restrict__ out) {
    int row = blockIdx.x;
    const float* xr = x + (size_t)row * E_;
    float s = 0.f, s2 = 0.f;
    for (int i = threadIdx.x; i < E_; i += 256) {
        float v = xr[i];
        s += v; s2 += v * v;
    }
    __shared__ float sh[32];
    #pragma unroll
    for (int o = 16; o > 0; o >>= 1) {
        s  += __shfl_down_sync(0xffffffffu, s, o);
        s2 += __shfl_down_sync(0xffffffffu, s2, o);
    }
    int w = threadIdx.x >> 5, l = threadIdx.x & 31;
    if (l == 0) { sh[w] = s; sh[w + 8] = s2; }
    __syncthreads();
    if (threadIdx.x == 0) {
        float ts = 0.f, ts2 = 0.f;
        #pragma unroll
        for (int i = 0; i < 8; i++) { ts += sh[i]; ts2 += sh[i + 8]; }
        float mean = ts / E_;
        float var = ts2 / E_ - mean * mean;
        sh[16] = mean;
        sh[17] = rsqrtf(var + 1e-6f);
    }
    __syncthreads();
    float mean = sh[16], inv = sh[17];
    for (int i = threadIdx.x; i < E_; i += 256) {
        out[(size_t)row * E_ + i] = (xr[i] - mean) * inv * g[i] + b[i];
    }
}

// ---------------- tf32 tensor-core GEMM (unchanged from R2) ----------------
#define AS_STRIDE 20
#define BS_STRIDE 136
template <int MODE>
__global__ __launch_bounds__(256) void gemm_tf32(const float* __restrict__ A,
                                                 const float* __restrict__ B,
                                                 const float* __restrict__ bias,
                                                 const float* __restrict__ R,
                                                 float* __restrict__ C,
                                                 int M, int N, int K) {
    __shared__ uint32_t As[2][128 * AS_STRIDE];
    __shared__ uint32_t Bs[2][16 * BS_STRIDE];

    const int t = threadIdx.x;
    const int warp = t >> 5, lane = t & 31;
    const int g = lane >> 2, tg = lane & 3;
    const int wm = warp >> 1, wn = warp & 1;
    const int m0 = blockIdx.y * 128, n0 = blockIdx.x * 128;

    float acc[2][8][4];
    #pragma unroll
    for (int mt = 0; mt < 2; mt++)
        #pragma unroll
        for (int nt = 0; nt < 8; nt++)
            #pragma unroll
            for (int r = 0; r < 4; r++) acc[mt][nt][r] = 0.f;

    const float* Ap = A + (size_t)m0 * K;
    const float* Bp = B + n0;

    float4 ra[2], rb[2];

    #define LDG_TILE(k0)                                                              \
        {                                                                             \
            _Pragma("unroll")                                                         \
            for (int i = 0; i < 2; i++) {                                             \
                int idx = t + 256 * i;                                                \
                ra[i] = *(const float4*)(Ap + (size_t)(idx >> 2) * K + (k0) + (idx & 3) * 4); \
                rb[i] = *(const float4*)(Bp + (size_t)((k0) + (idx >> 5)) * N + (idx & 31) * 4); \
            }                                                                         \
        }

    #define STS_TILE(buf)                                                             \
        {                                                                             \
            _Pragma("unroll")                                                         \
            for (int i = 0; i < 2; i++) {                                             \
                int idx = t + 256 * i;                                                \
                uint4 va = make_uint4(f2tf(ra[i].x), f2tf(ra[i].y), f2tf(ra[i].z), f2tf(ra[i].w)); \
                *(uint4*)&As[buf][(idx >> 2) * AS_STRIDE + (idx & 3) * 4] = va;       \
                uint4 vb = make_uint4(f2tf(rb[i].x), f2tf(rb[i].y), f2tf(rb[i].z), f2tf(rb[i].w)); \
                *(uint4*)&Bs[buf][(idx >> 5) * BS_STRIDE + (idx & 31) * 4] = vb;      \
            }                                                                         \
        }

    const int NK = K / 16;
    LDG_TILE(0);
    STS_TILE(0);
    __syncthreads();

    for (int it = 0; it < NK; it++) {
        if (it + 1 < NK) LDG_TILE((it + 1) * 16);
        const int buf = it & 1;
        #pragma unroll
        for (int ks = 0; ks < 2; ks++) {
            uint32_t af[2][4];
            #pragma unroll
            for (int mt = 0; mt < 2; mt++) {
                const uint32_t* ab = &As[buf][(wm * 32 + mt * 16 + g) * AS_STRIDE + ks * 8 + tg];
                af[mt][0] = ab[0];
                af[mt][1] = ab[8 * AS_STRIDE];
                af[mt][2] = ab[4];
                af[mt][3] = ab[8 * AS_STRIDE + 4];
            }
            #pragma unroll
            for (int nt = 0; nt < 8; nt++) {
                const uint32_t* bb = &Bs[buf][(ks * 8 + tg) * BS_STRIDE + wn * 64 + nt * 8 + g];
                uint32_t b0 = bb[0];
                uint32_t b1 = bb[4 * BS_STRIDE];
                #pragma unroll
                for (int mt = 0; mt < 2; mt++) mma_tf32(acc[mt][nt], af[mt], b0, b1);
            }
        }
        if (it + 1 < NK) {
            STS_TILE((it + 1) & 1);
            __syncthreads();
        }
    }

    #pragma unroll
    for (int mt = 0; mt < 2; mt++) {
        int r0 = m0 + wm * 32 + mt * 16 + g;
        int r1 = r0 + 8;
        #pragma unroll
        for (int nt = 0; nt < 8; nt++) {
            int col = n0 + wn * 64 + nt * 8 + tg * 2;
            float b0 = bias[col], b1 = bias[col + 1];
            float v0 = acc[mt][nt][0] + b0;
            float v1 = acc[mt][nt][1] + b1;
            float v2 = acc[mt][nt][2] + b0;
            float v3 = acc[mt][nt][3] + b1;
            if (MODE == 1) {
                v0 = v0 / (1.f + __expf(-1.702f * v0));
                v1 = v1 / (1.f + __expf(-1.702f * v1));
                v2 = v2 / (1.f + __expf(-1.702f * v2));
                v3 = v3 / (1.f + __expf(-1.702f * v3));
            }
            if (MODE == 2) {
                float2 rr0 = *(const float2*)&R[(size_t)r0 * N + col];
                float2 rr1 = *(const float2*)&R[(size_t)r1 * N + col];
                v0 += rr0.x; v1 += rr0.y; v2 += rr1.x; v3 += rr1.y;
            }
            *(float2*)&C[(size_t)r0 * N + col] = make_float2(v0, v1);
            *(float2*)&C[(size_t)r1 * N + col] = make_float2(v2, v3);
        }
    }
}

// ---------------- RoPE + head split ----------------
__global__ __launch_bounds__(256) void rope_kernel(const float* __restrict__ qkv,
                                                   const float* __restrict__ cosp,
                                                   const float* __restrict__ sinp,
                                                   float* __restrict__ q,
                                                   float* __restrict__ k,
                                                   float* __restrict__ v) {
    int idx = blockIdx.x * 256 + threadIdx.x;
    if (idx >= S_ * H_ * D_) return;
    int d = idx % D_;
    int h = (idx / D_) % H_;
    int s = idx / (H_ * D_);
    float c = cosp[s * D_ + d], sn = sinp[s * D_ + d];
    size_t base = (size_t)s * E3_ + h * D_;
    float qv = qkv[base + d];
    float kv = qkv[base + E_ + d];
    float vv = qkv[base + 2 * E_ + d];
    int dro = (d < 40) ? d + 40 : d - 40;
    float sgn = (d < 40) ? -1.f : 1.f;
    float qr = sgn * qkv[base + dro];
    float kr = sgn * qkv[base + E_ + dro];
    size_t o = ((size_t)h * S_ + s) * D_ + d;
    q[o] = qv * c + qr * sn;
    k[o] = kv * c + kr * sn;
    v[o] = vv;
}

// ---------------- Tensor-core flash attention (tf32 mma, online softmax) ----------------
// Block: head = blockIdx.y, 64 q rows = blockIdx.x*64. 256 threads = 8 warps.
// Warp (wm 0..3, wn 0..1). QK: warp tile m16 x n32 (4 n8-tiles), k=80.
// PV: warp tile m16 x n40 (5 n8-tiles), k=64.
#define QS 84   // Qs/Ks word stride (conflict-free frag loads: (20g+tg)&31 distinct)
#define VS 88   // Vs word stride (B-frag: (24tg+g)&31 distinct)
#define PS 68   // Ps word stride (A-frag: (4g+tg)&31 distinct)
#define ATTN_SMEM_WORDS (64*QS + 64*QS + 64*VS + 64*PS + 448)
#define ATTN_SMEM_BYTES (ATTN_SMEM_WORDS * 4)

__global__ __launch_bounds__(256) void attn_tc(const float* __restrict__ Q,
                                               const float* __restrict__ K,
                                               const float* __restrict__ V,
                                               float* __restrict__ out) {
    extern __shared__ uint32_t sm[];
    uint32_t* Qs = sm;                 // [64][QS]
    uint32_t* Ks = Qs + 64 * QS;       // [64][QS]
    uint32_t* Vs = Ks + 64 * QS;       // [64][VS]
    uint32_t* Ps = Vs + 64 * VS;       // [64][PS]
    float* mrow = (float*)(Ps + 64 * PS);
    float* lrow = mrow + 64;
    float* arow = lrow + 64;
    float* pm   = arow + 64;           // [64][2]
    float* ps   = pm + 128;            // [64][2]

    const int t = threadIdx.x;
    const int warp = t >> 5, lane = t & 31;
    const int g = lane >> 2, tg = lane & 3;
    const int wm = warp >> 1, wn = warp & 1;
    const int h = blockIdx.y;
    const int q0 = blockIdx.x * 64;
    const size_t hb = (size_t)h * S_ * D_;
    const float scale = 0.1118033988749895f;  // 1/sqrt(80)

    // load Q tile (scale folded in, tf32)
    #pragma unroll
    for (int i = 0; i < 5; i++) {
        int idx = t + 256 * i;               // 0..1279
        int r = idx / 20, c4 = (idx % 20) * 4;
        float4 v = *(const float4*)(Q + hb + (size_t)(q0 + r) * D_ + c4);
        uint4 w = make_uint4(f2tf(v.x * scale), f2tf(v.y * scale),
                             f2tf(v.z * scale), f2tf(v.w * scale));
        *(uint4*)&Qs[r * QS + c4] = w;
    }
    if (t < 64) { mrow[t] = -3.0e38f; lrow[t] = 0.f; }

    float oacc[5][4];
    #pragma unroll
    for (int nt = 0; nt < 5; nt++)
        #pragma unroll
        for (int r = 0; r < 4; r++) oacc[nt][r] = 0.f;

    const int r0 = wm * 16 + g, r1 = r0 + 8;

    for (int k0 = 0; k0 < S_; k0 += 64) {
        __syncthreads();  // Ks/Vs/Ps free (prev PV done); Q ready (iter 0)
        #pragma unroll
        for (int i = 0; i < 5; i++) {
            int idx = t + 256 * i;
            int r = idx / 20, c4 = (idx % 20) * 4;
            size_t off = hb + (size_t)(k0 + r) * D_ + c4;
            float4 kv = *(const float4*)(K + off);
            float4 vv = *(const float4*)(V + off);
            *(uint4*)&Ks[r * QS + c4] =
                make_uint4(f2tf(kv.x), f2tf(kv.y), f2tf(kv.z), f2tf(kv.w));
            *(uint4*)&Vs[r * VS + c4] =
                make_uint4(f2tf(vv.x), f2tf(vv.y), f2tf(vv.z), f2tf(vv.w));
        }
        __syncthreads();

        // ---- S = Q K^T (scaled) ----
        float sacc[4][4];
        #pragma unroll
        for (int nt = 0; nt < 4; nt++)
            #pragma unroll
            for (int r = 0; r < 4; r++) sacc[nt][r] = 0.f;

        #pragma unroll
        for (int ks = 0; ks < 10; ks++) {
            uint32_t af[4];
            const uint32_t* ab = &Qs[r0 * QS + ks * 8 + tg];
            af[0] = ab[0];
            af[1] = ab[8 * QS];
            af[2] = ab[4];
            af[3] = ab[8 * QS + 4];
            #pragma unroll
            for (int nt = 0; nt < 4; nt++) {
                const uint32_t* bb = &Ks[(wn * 32 + nt * 8 + g) * QS + ks * 8 + tg];
                mma_tf32(sacc[nt], af, bb[0], bb[4]);
            }
        }

        // ---- row max partials (quad shuffle over tg) ----
        float m0 = -3.0e38f, m1 = -3.0e38f;
        #pragma unroll
        for (int nt = 0; nt < 4; nt++) {
            m0 = fmaxf(m0, fmaxf(sacc[nt][0], sacc[nt][1]));
            m1 = fmaxf(m1, fmaxf(sacc[nt][2], sacc[nt][3]));
        }
        m0 = fmaxf(m0, __shfl_xor_sync(0xffffffffu, m0, 1));
        m0 = fmaxf(m0, __shfl_xor_sync(0xffffffffu, m0, 2));
        m1 = fmaxf(m1, __shfl_xor_sync(0xffffffffu, m1, 1));
        m1 = fmaxf(m1, __shfl_xor_sync(0xffffffffu, m1, 2));
        if (tg == 0) { pm[r0 * 2 + wn] = m0; pm[r1 * 2 + wn] = m1; }
        __syncthreads();

        if (t < 64) {
            float mn = fmaxf(mrow[t], fmaxf(pm[t * 2], pm[t * 2 + 1]));
            arow[t] = __expf(mrow[t] - mn);
            mrow[t] = mn;
        }
        __syncthreads();

        // ---- exp, write P (tf32), row-sum partials, rescale O ----
        float mv0 = mrow[r0], mv1 = mrow[r1];
        float s0 = 0.f, s1 = 0.f;
        #pragma unroll
        for (int nt = 0; nt < 4; nt++) {
            float e0 = __expf(sacc[nt][0] - mv0);
            float e1 = __expf(sacc[nt][1] - mv0);
            float e2 = __expf(sacc[nt][2] - mv1);
            float e3 = __expf(sacc[nt][3] - mv1);
            s0 += e0 + e1; s1 += e2 + e3;
            int cb = wn * 32 + nt * 8 + 2 * tg;
            *(uint2*)&Ps[r0 * PS + cb] = make_uint2(f2tf(e0), f2tf(e1));
            *(uint2*)&Ps[r1 * PS + cb] = make_uint2(f2tf(e2), f2tf(e3));
        }
        s0 += __shfl_xor_sync(0xffffffffu, s0, 1);
        s0 += __shfl_xor_sync(0xffffffffu, s0, 2);
        s1 += __shfl_xor_sync(0xffffffffu, s1, 1);
        s1 += __shfl_xor_sync(0xffffffffu, s1, 2);
        if (tg == 0) { ps[r0 * 2 + wn] = s0; ps[r1 * 2 + wn] = s1; }

        float a0 = arow[r0], a1 = arow[r1];
        #pragma unroll
        for (int nt = 0; nt < 5; nt++) {
            oacc[nt][0] *= a0; oacc[nt][1] *= a0;
            oacc[nt][2] *= a1; oacc[nt][3] *= a1;
        }
        __syncthreads();

        if (t < 64) lrow[t] = lrow[t] * arow[t] + ps[t * 2] + ps[t * 2 + 1];

        // ---- O += P V ----
        #pragma unroll
        for (int kc = 0; kc < 8; kc++) {
            uint32_t af[4];
            const uint32_t* ab = &Ps[r0 * PS + kc * 8 + tg];
            af[0] = ab[0];
            af[1] = ab[8 * PS];
            af[2] = ab[4];
            af[3] = ab[8 * PS + 4];
            #pragma unroll
            for (int nt = 0; nt < 5; nt++) {
                const uint32_t* bb = &Vs[(kc * 8 + tg) * VS + wn * 40 + nt * 8 + g];
                mma_tf32(oacc[nt], af, bb[0], bb[4 * VS]);
            }
        }
    }
    __syncthreads();

    float inv0 = 1.f / lrow[r0], inv1 = 1.f / lrow[r1];
    #pragma unroll
    for (int nt = 0; nt < 5; nt++) {
        int col = h * D_ + wn * 40 + nt * 8 + 2 * tg;
        *(float2*)&out[(size_t)(q0 + r0) * E_ + col] =
            make_float2(oacc[nt][0] * inv0, oacc[nt][1] * inv0);
        *(float2*)&out[(size_t)(q0 + r1) * E_ + col] =
            make_float2(oacc[nt][2] * inv1, oacc[nt][3] * inv1);
    }
}

// ---------------- launch ----------------
extern "C" void kernel_launch(void* const* d_in, const int* in_sizes, int n_in,
                              void* d_out, int out_size) {
    const float* x    = (const float*)d_in[0];
    // d_in[1] = attention_mask (all true) — unused
    const float* cosp = (const float*)d_in[2];
    const float* sinp = (const float*)d_in[3];
    const float* ln1g = (const float*)d_in[4];
    const float* ln1b = (const float*)d_in[5];
    const float* ln2g = (const float*)d_in[6];
    const float* ln2b = (const float*)d_in[7];
    const float* wqkv = (const float*)d_in[8];
    const float* bqkv = (const float*)d_in[9];
    const float* wo   = (const float*)d_in[10];
    const float* bo   = (const float*)d_in[11];
    const float* wfc1 = (const float*)d_in[12];
    const float* bfc1 = (const float*)d_in[13];
    const float* wfc2 = (const float*)d_in[14];
    const float* bfc2 = (const float*)d_in[15];
    float* out = (float*)d_out;

    float *lnp, *qkvp, *qp, *kp, *vp, *attnp, *x1p, *ln2p, *fc1p;
    cudaGetSymbolAddress((void**)&lnp,   g_ln);
    cudaGetSymbolAddress((void**)&qkvp,  g_qkv);
    cudaGetSymbolAddress((void**)&qp,    g_q);
    cudaGetSymbolAddress((void**)&kp,    g_k);
    cudaGetSymbolAddress((void**)&vp,    g_v);
    cudaGetSymbolAddress((void**)&attnp, g_attn);
    cudaGetSymbolAddress((void**)&x1p,   g_x1);
    cudaGetSymbolAddress((void**)&ln2p,  g_ln2);
    cudaGetSymbolAddress((void**)&fc1p,  g_fc1);

    // opt into >48KB dynamic smem for the attention kernel (idempotent)
    cudaFuncSetAttribute(attn_tc, cudaFuncAttributeMaxDynamicSharedMemorySize,
                         ATTN_SMEM_BYTES);

    // 1. LN1
    ln_kernel<<<S_, 256>>>(x, ln1g, ln1b, lnp);
    // 2. QKV = ln1 @ w_qkv + b_qkv      [2048,1280]x[1280,3840]
    gemm_tf32<0><<<dim3(E3_ / 128, S_ / 128), 256>>>(lnp, wqkv, bqkv, nullptr, qkvp, S_, E3_, E_);
    // 3. RoPE + split into head-major q/k/v
    rope_kernel<<<(S_ * H_ * D_) / 256, 256>>>(qkvp, cosp, sinp, qp, kp, vp);
    // 4. Attention (tensor-core flash, online softmax), writes [S, E] directly
    attn_tc<<<dim3(S_ / 64, H_), 256, ATTN_SMEM_BYTES>>>(qp, kp, vp, attnp);
    // 5. x1 = x + attn @ w_o + b_o
    gemm_tf32<2><<<dim3(E_ / 128, S_ / 128), 256>>>(attnp, wo, bo, x, x1p, S_, E_, E_);
    // 6. LN2
    ln_kernel<<<S_, 256>>>(x1p, ln2g, ln2b, ln2p);
    // 7. fc1 = quickgelu(ln2 @ w_fc1 + b_fc1)    [2048,1280]x[1280,5120]
    gemm_tf32<1><<<dim3(F_ / 128, S_ / 128), 256>>>(ln2p, wfc1, bfc1, nullptr, fc1p, S_, F_, E_);
    // 8. out = x1 + fc1 @ w_fc2 + b_fc2          [2048,5120]x[5120,1280]
    gemm_tf32<2><<<dim3(E_ / 128, S_ / 128), 256>>>(fc1p, wfc2, bfc2, x1p, out, S_, E_, F_);
}

// round 14
// speedup vs baseline: 1.8916x; 1.1602x over previous
#include <cuda_runtime.h>
#include <stdint.h>
#include <math.h>

#define S_ 2048
#define E_ 1280
#define H_ 16
#define D_ 80
#define F_ 5120
#define E3_ 3840

// ---------------- scratch (device globals; no runtime allocation) ----------------
__device__ float g_ln[S_ * E_];
__device__ float g_qkv[S_ * E3_];
__device__ float g_q[H_ * S_ * D_];
__device__ float g_k[H_ * S_ * D_];
__device__ float g_v[H_ * S_ * D_];
__device__ float g_attn[S_ * E_];
__device__ float g_x1[S_ * E_];
__device__ float g_ln2[S_ * E_];
__device__ float g_fc1[S_ * F_];

// ---------------- helpers ----------------
__device__ __forceinline__ uint32_t f2tf(float x) {
    uint32_t r;
    asm("cvt.rna.tf32.f32 %0, %1;" : "=r"(r) : "f"(x));
    return r;
}

__device__ __forceinline__ void mma_tf32(float* c, const uint32_t* a, uint32_t b0, uint32_t b1) {
    asm volatile(
        "mma.sync.aligned.m16n8k8.row.col.f32.tf32.tf32.f32 "
        "{%0,%1,%2,%3}, {%4,%5,%6,%7}, {%8,%9}, {%0,%1,%2,%3};\n"
        : "+f"(c[0]), "+f"(c[1]), "+f"(c[2]), "+f"(c[3])
        : "r"(a[0]), "r"(a[1]), "r"(a[2]), "r"(a[3]), "r"(b0), "r"(b1));
}

__device__ __forceinline__ void cp_async16(uint32_t dst, const float* src) {
    asm volatile("cp.async.cg.shared.global [%0], [%1], 16;\n" :: "r"(dst), "l"(src));
}

// ---------------- LayerNorm ----------------
__global__ __launch_bounds__(256) void ln_kernel(const float* __restrict__ x,
                                                 const float* __restrict__ g,
                                                 const float* __restrict__ b,
                                                 float* __restrict__ out) {
    int row = blockIdx.x;
    const float* xr = x + (size_t)row * E_;
    float s = 0.f, s2 = 0.f;
    for (int i = threadIdx.x; i < E_; i += 256) {
        float v = xr[i];
        s += v; s2 += v * v;
    }
    __shared__ float sh[32];
    #pragma unroll
    for (int o = 16; o > 0; o >>= 1) {
        s  += __shfl_down_sync(0xffffffffu, s, o);
        s2 += __shfl_down_sync(0xffffffffu, s2, o);
    }
    int w = threadIdx.x >> 5, l = threadIdx.x & 31;
    if (l == 0) { sh[w] = s; sh[w + 8] = s2; }
    __syncthreads();
    if (threadIdx.x == 0) {
        float ts = 0.f, ts2 = 0.f;
        #pragma unroll
        for (int i = 0; i < 8; i++) { ts += sh[i]; ts2 += sh[i + 8]; }
        float mean = ts / E_;
        float var = ts2 / E_ - mean * mean;
        sh[16] = mean;
        sh[17] = rsqrtf(var + 1e-6f);
    }
    __syncthreads();
    float mean = sh[16], inv = sh[17];
    for (int i = threadIdx.x; i < E_; i += 256) {
        out[(size_t)row * E_ + i] = (xr[i] - mean) * inv * g[i] + b[i];
    }
}

// ---------------- tf32 tensor-core GEMM, 4-stage cp.async pipeline ----------------
// C[M,N] = A[M,K] @ B[K,N] + bias (+epilogue)
// MODE 0: bias only.  MODE 1: bias + quickGELU.  MODE 2: bias + residual R.
// 128x128 block tile, k-tile 16, 256 threads, warp tile 32x64 (2x8 m16n8k8 tf32).
// fp32 staged raw in smem; mma truncates to tf32 (rz).
#define AS_STRIDE 20
#define BS_STRIDE 136
#define GEMM_STAGES 4
#define GEMM_SMEM_WORDS (GEMM_STAGES * (128 * AS_STRIDE + 16 * BS_STRIDE))
#define GEMM_SMEM_BYTES (GEMM_SMEM_WORDS * 4)

template <int MODE>
__global__ __launch_bounds__(256, 2) void gemm_tf32(const float* __restrict__ A,
                                                    const float* __restrict__ B,
                                                    const float* __restrict__ bias,
                                                    const float* __restrict__ R,
                                                    float* __restrict__ C,
                                                    int M, int N, int K) {
    extern __shared__ uint32_t gsm[];
    uint32_t* As = gsm;                                    // [STAGES][128*AS_STRIDE]
    uint32_t* Bs = gsm + GEMM_STAGES * 128 * AS_STRIDE;    // [STAGES][16*BS_STRIDE]

    const int t = threadIdx.x;
    const int warp = t >> 5, lane = t & 31;
    const int g = lane >> 2, tg = lane & 3;
    const int wm = warp >> 1, wn = warp & 1;
    const int m0 = blockIdx.y * 128, n0 = blockIdx.x * 128;

    float acc[2][8][4];
    #pragma unroll
    for (int mt = 0; mt < 2; mt++)
        #pragma unroll
        for (int nt = 0; nt < 8; nt++)
            #pragma unroll
            for (int r = 0; r < 4; r++) acc[mt][nt][r] = 0.f;

    const float* Ap = A + (size_t)m0 * K;
    const float* Bp = B + n0;
    const uint32_t a_base = (uint32_t)__cvta_generic_to_shared(As);
    const uint32_t b_base = (uint32_t)__cvta_generic_to_shared(Bs);

    // A: row = idx>>2 (0..127), k chunk = (idx&3)*4.  B: k row = idx>>5, col = (idx&31)*4.
    #define ISSUE_TILE(k0, buf)                                                             \
        {                                                                                   \
            _Pragma("unroll")                                                               \
            for (int i = 0; i < 2; i++) {                                                   \
                int idx = t + 256 * i;                                                      \
                cp_async16(a_base + (uint32_t)(((buf) * 128 * AS_STRIDE +                   \
                                (idx >> 2) * AS_STRIDE + (idx & 3) * 4) * 4),               \
                           Ap + (size_t)(idx >> 2) * K + (k0) + (idx & 3) * 4);             \
                cp_async16(b_base + (uint32_t)(((buf) * 16 * BS_STRIDE +                    \
                                (idx >> 5) * BS_STRIDE + (idx & 31) * 4) * 4),              \
                           Bp + (size_t)((k0) + (idx >> 5)) * N + (idx & 31) * 4);          \
            }                                                                               \
            asm volatile("cp.async.commit_group;");                                        \
        }

    const int NK = K / 16;
    #pragma unroll
    for (int s = 0; s < GEMM_STAGES - 1; s++) ISSUE_TILE(s * 16, s);

    for (int it = 0; it < NK; it++) {
        asm volatile("cp.async.wait_group %0;" :: "n"(GEMM_STAGES - 2));
        __syncthreads();
        int nf = it + GEMM_STAGES - 1;
        if (nf < NK) {
            ISSUE_TILE(nf * 16, nf & (GEMM_STAGES - 1));
        } else {
            asm volatile("cp.async.commit_group;");
        }
        const uint32_t* Asb = As + (it & (GEMM_STAGES - 1)) * 128 * AS_STRIDE;
        const uint32_t* Bsb = Bs + (it & (GEMM_STAGES - 1)) * 16 * BS_STRIDE;
        #pragma unroll
        for (int ks = 0; ks < 2; ks++) {
            uint32_t af[2][4];
            #pragma unroll
            for (int mt = 0; mt < 2; mt++) {
                const uint32_t* ab = &Asb[(wm * 32 + mt * 16 + g) * AS_STRIDE + ks * 8 + tg];
                af[mt][0] = ab[0];
                af[mt][1] = ab[8 * AS_STRIDE];
                af[mt][2] = ab[4];
                af[mt][3] = ab[8 * AS_STRIDE + 4];
            }
            #pragma unroll
            for (int nt = 0; nt < 8; nt++) {
                const uint32_t* bb = &Bsb[(ks * 8 + tg) * BS_STRIDE + wn * 64 + nt * 8 + g];
                uint32_t b0 = bb[0];
                uint32_t b1 = bb[4 * BS_STRIDE];
                #pragma unroll
                for (int mt = 0; mt < 2; mt++) mma_tf32(acc[mt][nt], af[mt], b0, b1);
            }
        }
    }

    // ---- epilogue ----
    #pragma unroll
    for (int mt = 0; mt < 2; mt++) {
        int r0 = m0 + wm * 32 + mt * 16 + g;
        int r1 = r0 + 8;
        #pragma unroll
        for (int nt = 0; nt < 8; nt++) {
            int col = n0 + wn * 64 + nt * 8 + tg * 2;
            float b0 = bias[col], b1 = bias[col + 1];
            float v0 = acc[mt][nt][0] + b0;
            float v1 = acc[mt][nt][1] + b1;
            float v2 = acc[mt][nt][2] + b0;
            float v3 = acc[mt][nt][3] + b1;
            if (MODE == 1) {
                v0 = v0 / (1.f + __expf(-1.702f * v0));
                v1 = v1 / (1.f + __expf(-1.702f * v1));
                v2 = v2 / (1.f + __expf(-1.702f * v2));
                v3 = v3 / (1.f + __expf(-1.702f * v3));
            }
            if (MODE == 2) {
                float2 rr0 = *(const float2*)&R[(size_t)r0 * N + col];
                float2 rr1 = *(const float2*)&R[(size_t)r1 * N + col];
                v0 += rr0.x; v1 += rr0.y; v2 += rr1.x; v3 += rr1.y;
            }
            *(float2*)&C[(size_t)r0 * N + col] = make_float2(v0, v1);
            *(float2*)&C[(size_t)r1 * N + col] = make_float2(v2, v3);
        }
    }
}

// ---------------- RoPE + head split ----------------
__global__ __launch_bounds__(256) void rope_kernel(const float* __restrict__ qkv,
                                                   const float* __restrict__ cosp,
                                                   const float* __restrict__ sinp,
                                                   float* __restrict__ q,
                                                   float* __restrict__ k,
                                                   float* __restrict__ v) {
    int idx = blockIdx.x * 256 + threadIdx.x;
    if (idx >= S_ * H_ * D_) return;
    int d = idx % D_;
    int h = (idx / D_) % H_;
    int s = idx / (H_ * D_);
    float c = cosp[s * D_ + d], sn = sinp[s * D_ + d];
    size_t base = (size_t)s * E3_ + h * D_;
    float qv = qkv[base + d];
    float kv = qkv[base + E_ + d];
    float vv = qkv[base + 2 * E_ + d];
    int dro = (d < 40) ? d + 40 : d - 40;
    float sgn = (d < 40) ? -1.f : 1.f;
    float qr = sgn * qkv[base + dro];
    float kr = sgn * qkv[base + E_ + dro];
    size_t o = ((size_t)h * S_ + s) * D_ + d;
    q[o] = qv * c + qr * sn;
    k[o] = kv * c + kr * sn;
    v[o] = vv;
}

// ---------------- Tensor-core flash attention (tf32 mma, online softmax) ----------------
#define QS 84
#define VS 88
#define PS 68
#define ATTN_SMEM_WORDS (64*QS + 64*QS + 64*VS + 64*PS + 448)
#define ATTN_SMEM_BYTES (ATTN_SMEM_WORDS * 4)

__global__ __launch_bounds__(256) void attn_tc(const float* __restrict__ Q,
                                               const float* __restrict__ K,
                                               const float* __restrict__ V,
                                               float* __restrict__ out) {
    extern __shared__ uint32_t sm[];
    uint32_t* Qs = sm;
    uint32_t* Ks = Qs + 64 * QS;
    uint32_t* Vs = Ks + 64 * QS;
    uint32_t* Ps = Vs + 64 * VS;
    float* mrow = (float*)(Ps + 64 * PS);
    float* lrow = mrow + 64;
    float* arow = lrow + 64;
    float* pm   = arow + 64;
    float* ps   = pm + 128;

    const int t = threadIdx.x;
    const int warp = t >> 5, lane = t & 31;
    const int g = lane >> 2, tg = lane & 3;
    const int wm = warp >> 1, wn = warp & 1;
    const int h = blockIdx.y;
    const int q0 = blockIdx.x * 64;
    const size_t hb = (size_t)h * S_ * D_;
    const float scale = 0.1118033988749895f;

    #pragma unroll
    for (int i = 0; i < 5; i++) {
        int idx = t + 256 * i;
        int r = idx / 20, c4 = (idx % 20) * 4;
        float4 v = *(const float4*)(Q + hb + (size_t)(q0 + r) * D_ + c4);
        uint4 w = make_uint4(f2tf(v.x * scale), f2tf(v.y * scale),
                             f2tf(v.z * scale), f2tf(v.w * scale));
        *(uint4*)&Qs[r * QS + c4] = w;
    }
    if (t < 64) { mrow[t] = -3.0e38f; lrow[t] = 0.f; }

    float oacc[5][4];
    #pragma unroll
    for (int nt = 0; nt < 5; nt++)
        #pragma unroll
        for (int r = 0; r < 4; r++) oacc[nt][r] = 0.f;

    const int r0 = wm * 16 + g, r1 = r0 + 8;

    for (int k0 = 0; k0 < S_; k0 += 64) {
        __syncthreads();
        #pragma unroll
        for (int i = 0; i < 5; i++) {
            int idx = t + 256 * i;
            int r = idx / 20, c4 = (idx % 20) * 4;
            size_t off = hb + (size_t)(k0 + r) * D_ + c4;
            float4 kv = *(const float4*)(K + off);
            float4 vv = *(const float4*)(V + off);
            *(uint4*)&Ks[r * QS + c4] =
                make_uint4(f2tf(kv.x), f2tf(kv.y), f2tf(kv.z), f2tf(kv.w));
            *(uint4*)&Vs[r * VS + c4] =
                make_uint4(f2tf(vv.x), f2tf(vv.y), f2tf(vv.z), f2tf(vv.w));
        }
        __syncthreads();

        float sacc[4][4];
        #pragma unroll
        for (int nt = 0; nt < 4; nt++)
            #pragma unroll
            for (int r = 0; r < 4; r++) sacc[nt][r] = 0.f;

        #pragma unroll
        for (int ks = 0; ks < 10; ks++) {
            uint32_t af[4];
            const uint32_t* ab = &Qs[r0 * QS + ks * 8 + tg];
            af[0] = ab[0];
            af[1] = ab[8 * QS];
            af[2] = ab[4];
            af[3] = ab[8 * QS + 4];
            #pragma unroll
            for (int nt = 0; nt < 4; nt++) {
                const uint32_t* bb = &Ks[(wn * 32 + nt * 8 + g) * QS + ks * 8 + tg];
                mma_tf32(sacc[nt], af, bb[0], bb[4]);
            }
        }

        float m0 = -3.0e38f, m1 = -3.0e38f;
        #pragma unroll
        for (int nt = 0; nt < 4; nt++) {
            m0 = fmaxf(m0, fmaxf(sacc[nt][0], sacc[nt][1]));
            m1 = fmaxf(m1, fmaxf(sacc[nt][2], sacc[nt][3]));
        }
        m0 = fmaxf(m0, __shfl_xor_sync(0xffffffffu, m0, 1));
        m0 = fmaxf(m0, __shfl_xor_sync(0xffffffffu, m0, 2));
        m1 = fmaxf(m1, __shfl_xor_sync(0xffffffffu, m1, 1));
        m1 = fmaxf(m1, __shfl_xor_sync(0xffffffffu, m1, 2));
        if (tg == 0) { pm[r0 * 2 + wn] = m0; pm[r1 * 2 + wn] = m1; }
        __syncthreads();

        if (t < 64) {
            float mn = fmaxf(mrow[t], fmaxf(pm[t * 2], pm[t * 2 + 1]));
            arow[t] = __expf(mrow[t] - mn);
            mrow[t] = mn;
        }
        __syncthreads();

        float mv0 = mrow[r0], mv1 = mrow[r1];
        float s0 = 0.f, s1 = 0.f;
        #pragma unroll
        for (int nt = 0; nt < 4; nt++) {
            float e0 = __expf(sacc[nt][0] - mv0);
            float e1 = __expf(sacc[nt][1] - mv0);
            float e2 = __expf(sacc[nt][2] - mv1);
            float e3 = __expf(sacc[nt][3] - mv1);
            s0 += e0 + e1; s1 += e2 + e3;
            int cb = wn * 32 + nt * 8 + 2 * tg;
            *(uint2*)&Ps[r0 * PS + cb] = make_uint2(f2tf(e0), f2tf(e1));
            *(uint2*)&Ps[r1 * PS + cb] = make_uint2(f2tf(e2), f2tf(e3));
        }
        s0 += __shfl_xor_sync(0xffffffffu, s0, 1);
        s0 += __shfl_xor_sync(0xffffffffu, s0, 2);
        s1 += __shfl_xor_sync(0xffffffffu, s1, 1);
        s1 += __shfl_xor_sync(0xffffffffu, s1, 2);
        if (tg == 0) { ps[r0 * 2 + wn] = s0; ps[r1 * 2 + wn] = s1; }

        float a0 = arow[r0], a1 = arow[r1];
        #pragma unroll
        for (int nt = 0; nt < 5; nt++) {
            oacc[nt][0] *= a0; oacc[nt][1] *= a0;
            oacc[nt][2] *= a1; oacc[nt][3] *= a1;
        }
        __syncthreads();

        if (t < 64) lrow[t] = lrow[t] * arow[t] + ps[t * 2] + ps[t * 2 + 1];

        #pragma unroll
        for (int kc = 0; kc < 8; kc++) {
            uint32_t af[4];
            const uint32_t* ab = &Ps[r0 * PS + kc * 8 + tg];
            af[0] = ab[0];
            af[1] = ab[8 * PS];
            af[2] = ab[4];
            af[3] = ab[8 * PS + 4];
            #pragma unroll
            for (int nt = 0; nt < 5; nt++) {
                const uint32_t* bb = &Vs[(kc * 8 + tg) * VS + wn * 40 + nt * 8 + g];
                mma_tf32(oacc[nt], af, bb[0], bb[4 * VS]);
            }
        }
    }
    __syncthreads();

    float inv0 = 1.f / lrow[r0], inv1 = 1.f / lrow[r1];
    #pragma unroll
    for (int nt = 0; nt < 5; nt++) {
        int col = h * D_ + wn * 40 + nt * 8 + 2 * tg;
        *(float2*)&out[(size_t)(q0 + r0) * E_ + col] =
            make_float2(oacc[nt][0] * inv0, oacc[nt][1] * inv0);
        *(float2*)&out[(size_t)(q0 + r1) * E_ + col] =
            make_float2(oacc[nt][2] * inv1, oacc[nt][3] * inv1);
    }
}

// ---------------- launch ----------------
extern "C" void kernel_launch(void* const* d_in, const int* in_sizes, int n_in,
                              void* d_out, int out_size) {
    const float* x    = (const float*)d_in[0];
    // d_in[1] = attention_mask (all true) — unused
    const float* cosp = (const float*)d_in[2];
    const float* sinp = (const float*)d_in[3];
    const float* ln1g = (const float*)d_in[4];
    const float* ln1b = (const float*)d_in[5];
    const float* ln2g = (const float*)d_in[6];
    const float* ln2b = (const float*)d_in[7];
    const float* wqkv = (const float*)d_in[8];
    const float* bqkv = (const float*)d_in[9];
    const float* wo   = (const float*)d_in[10];
    const float* bo   = (const float*)d_in[11];
    const float* wfc1 = (const float*)d_in[12];
    const float* bfc1 = (const float*)d_in[13];
    const float* wfc2 = (const float*)d_in[14];
    const float* bfc2 = (const float*)d_in[15];
    float* out = (float*)d_out;

    float *lnp, *qkvp, *qp, *kp, *vp, *attnp, *x1p, *ln2p, *fc1p;
    cudaGetSymbolAddress((void**)&lnp,   g_ln);
    cudaGetSymbolAddress((void**)&qkvp,  g_qkv);
    cudaGetSymbolAddress((void**)&qp,    g_q);
    cudaGetSymbolAddress((void**)&kp,    g_k);
    cudaGetSymbolAddress((void**)&vp,    g_v);
    cudaGetSymbolAddress((void**)&attnp, g_attn);
    cudaGetSymbolAddress((void**)&x1p,   g_x1);
    cudaGetSymbolAddress((void**)&ln2p,  g_ln2);
    cudaGetSymbolAddress((void**)&fc1p,  g_fc1);

    // opt into large dynamic smem (idempotent)
    cudaFuncSetAttribute(attn_tc, cudaFuncAttributeMaxDynamicSharedMemorySize,
                         ATTN_SMEM_BYTES);
    cudaFuncSetAttribute(gemm_tf32<0>, cudaFuncAttributeMaxDynamicSharedMemorySize,
                         GEMM_SMEM_BYTES);
    cudaFuncSetAttribute(gemm_tf32<1>, cudaFuncAttributeMaxDynamicSharedMemorySize,
                         GEMM_SMEM_BYTES);
    cudaFuncSetAttribute(gemm_tf32<2>, cudaFuncAttributeMaxDynamicSharedMemorySize,
                         GEMM_SMEM_BYTES);

    // 1. LN1
    ln_kernel<<<S_, 256>>>(x, ln1g, ln1b, lnp);
    // 2. QKV = ln1 @ w_qkv + b_qkv      [2048,1280]x[1280,3840]
    gemm_tf32<0><<<dim3(E3_ / 128, S_ / 128), 256, GEMM_SMEM_BYTES>>>(lnp, wqkv, bqkv, nullptr, qkvp, S_, E3_, E_);
    // 3. RoPE + split into head-major q/k/v
    rope_kernel<<<(S_ * H_ * D_) / 256, 256>>>(qkvp, cosp, sinp, qp, kp, vp);
    // 4. Attention (tensor-core flash, online softmax), writes [S, E] directly
    attn_tc<<<dim3(S_ / 64, H_), 256, ATTN_SMEM_BYTES>>>(qp, kp, vp, attnp);
    // 5. x1 = x + attn @ w_o + b_o
    gemm_tf32<2><<<dim3(E_ / 128, S_ / 128), 256, GEMM_SMEM_BYTES>>>(attnp, wo, bo, x, x1p, S_, E_, E_);
    // 6. LN2
    ln_kernel<<<S_, 256>>>(x1p, ln2g, ln2b, ln2p);
    // 7. fc1 = quickgelu(ln2 @ w_fc1 + b_fc1)    [2048,1280]x[1280,5120]
    gemm_tf32<1><<<dim3(F_ / 128, S_ / 128), 256, GEMM_SMEM_BYTES>>>(ln2p, wfc1, bfc1, nullptr, fc1p, S_, F_, E_);
    // 8. out = x1 + fc1 @ w_fc2 + b_fc2          [2048,5120]x[5120,1280]
    gemm_tf32<2><<<dim3(E_ / 128, S_ / 128), 256, GEMM_SMEM_BYTES>>>(fc1p, wfc2, bfc2, x1p, out, S_, E_, F_);
}

// round 16
// speedup vs baseline: 1.9592x; 1.0357x over previous
#include <cuda_runtime.h>
#include <stdint.h>
#include <math.h>

#define S_ 2048
#define E_ 1280
#define H_ 16
#define D_ 80
#define F_ 5120
#define E3_ 3840

// ---------------- scratch (device globals; no runtime allocation) ----------------
__device__ float g_ln[S_ * E_];
__device__ float g_qkv[S_ * E3_];
__device__ float g_q[H_ * S_ * D_];
__device__ float g_k[H_ * S_ * D_];
__device__ float g_v[H_ * S_ * D_];
__device__ float g_attn[S_ * E_];
__device__ float g_x1[S_ * E_];
__device__ float g_ln2[S_ * E_];
__device__ float g_fc1[S_ * F_];
// tf32-rounded weight copies (rounded every launch; deterministic)
__device__ float g_wqkv_r[E_ * E3_];
__device__ float g_wo_r[E_ * E_];
__device__ float g_wfc1_r[E_ * F_];
__device__ float g_wfc2_r[F_ * E_];

// ---------------- helpers ----------------
__device__ __forceinline__ uint32_t f2tf(float x) {
    uint32_t r;
    asm("cvt.rna.tf32.f32 %0, %1;" : "=r"(r) : "f"(x));
    return r;
}
__device__ __forceinline__ float f2tf_f(float x) { return __uint_as_float(f2tf(x)); }

__device__ __forceinline__ void mma_tf32(float* c, const uint32_t* a, uint32_t b0, uint32_t b1) {
    asm volatile(
        "mma.sync.aligned.m16n8k8.row.col.f32.tf32.tf32.f32 "
        "{%0,%1,%2,%3}, {%4,%5,%6,%7}, {%8,%9}, {%0,%1,%2,%3};\n"
        : "+f"(c[0]), "+f"(c[1]), "+f"(c[2]), "+f"(c[3])
        : "r"(a[0]), "r"(a[1]), "r"(a[2]), "r"(a[3]), "r"(b0), "r"(b1));
}

__device__ __forceinline__ void cp_async16(uint32_t dst, const float* src) {
    asm volatile("cp.async.cg.shared.global [%0], [%1], 16;\n" :: "r"(dst), "l"(src));
}

// ---------------- weight pre-round (fp32 -> exact tf32 values, rna) ----------------
__global__ __launch_bounds__(256) void round_tf32(const float* __restrict__ in,
                                                  float* __restrict__ out) {
    int i = (blockIdx.x * 256 + threadIdx.x) * 4;
    float4 v = *(const float4*)(in + i);
    uint4 w = make_uint4(f2tf(v.x), f2tf(v.y), f2tf(v.z), f2tf(v.w));
    *(uint4*)(out + i) = w;
}

// ---------------- LayerNorm (output rounded to tf32 values) ----------------
__global__ __launch_bounds__(256) void ln_kernel(const float* __restrict__ x,
                                                 const float* __restrict__ g,
                                                 const float* __restrict__ b,
                                                 float* __restrict__ out) {
    int row = blockIdx.x;
    const float* xr = x + (size_t)row * E_;
    float s = 0.f, s2 = 0.f;
    for (int i = threadIdx.x; i < E_; i += 256) {
        float v = xr[i];
        s += v; s2 += v * v;
    }
    __shared__ float sh[32];
    #pragma unroll
    for (int o = 16; o > 0; o >>= 1) {
        s  += __shfl_down_sync(0xffffffffu, s, o);
        s2 += __shfl_down_sync(0xffffffffu, s2, o);
    }
    int w = threadIdx.x >> 5, l = threadIdx.x & 31;
    if (l == 0) { sh[w] = s; sh[w + 8] = s2; }
    __syncthreads();
    if (threadIdx.x == 0) {
        float ts = 0.f, ts2 = 0.f;
        #pragma unroll
        for (int i = 0; i < 8; i++) { ts += sh[i]; ts2 += sh[i + 8]; }
        float mean = ts / E_;
        float var = ts2 / E_ - mean * mean;
        sh[16] = mean;
        sh[17] = rsqrtf(var + 1e-6f);
    }
    __syncthreads();
    float mean = sh[16], inv = sh[17];
    for (int i = threadIdx.x; i < E_; i += 256) {
        out[(size_t)row * E_ + i] = f2tf_f((xr[i] - mean) * inv * g[i] + b[i]);
    }
}

// ---------------- tf32 tensor-core GEMM, 4-stage cp.async pipeline ----------------
// C[M,N] = A[M,K] @ B[K,N] + bias (+epilogue). Operands must be exact tf32 values.
// MODE 0: bias. MODE 1: bias + quickGELU (output tf32-rounded). MODE 2: bias + residual R.
// BM=128: 128x128 tile, warp 32x64 (occ 2). BM=64: 64x128 tile, warp 32x32 (occ 3).
#define AS_STRIDE 20
#define BS_STRIDE 136
#define GEMM_STAGES 4
#define GEMM_SMEM_WORDS(BM) (GEMM_STAGES * ((BM) * AS_STRIDE + 16 * BS_STRIDE))
#define GEMM_SMEM_BYTES(BM) (GEMM_SMEM_WORDS(BM) * 4)

template <int MODE, int BM>
__global__ __launch_bounds__(256, (BM == 64 ? 3 : 2))
void gemm_tf32(const float* __restrict__ A,
               const float* __restrict__ B,
               const float* __restrict__ bias,
               const float* __restrict__ R,
               float* __restrict__ C,
               int M, int N, int K) {
    extern __shared__ uint32_t gsm[];
    uint32_t* As = gsm;                                      // [STAGES][BM*AS_STRIDE]
    uint32_t* Bs = gsm + GEMM_STAGES * BM * AS_STRIDE;       // [STAGES][16*BS_STRIDE]

    constexpr int NT = (BM == 128) ? 8 : 4;
    constexpr int WN_OFF = (BM == 128) ? 64 : 32;
    constexpr int A_ITERS = BM / 64;

    const int t = threadIdx.x;
    const int warp = t >> 5, lane = t & 31;
    const int g = lane >> 2, tg = lane & 3;
    const int wm = (BM == 128) ? (warp >> 1) : (warp >> 2);
    const int wn = (BM == 128) ? (warp & 1) : (warp & 3);
    const int m0 = blockIdx.y * BM, n0 = blockIdx.x * 128;

    float acc[2][NT][4];
    #pragma unroll
    for (int mt = 0; mt < 2; mt++)
        #pragma unroll
        for (int nt = 0; nt < NT; nt++)
            #pragma unroll
            for (int r = 0; r < 4; r++) acc[mt][nt][r] = 0.f;

    const float* Ap = A + (size_t)m0 * K;
    const float* Bp = B + n0;
    const uint32_t a_base = (uint32_t)__cvta_generic_to_shared(As);
    const uint32_t b_base = (uint32_t)__cvta_generic_to_shared(Bs);

    #define ISSUE_TILE(k0, buf)                                                             \
        {                                                                                   \
            _Pragma("unroll")                                                               \
            for (int i = 0; i < A_ITERS; i++) {                                             \
                int idx = t + 256 * i;                                                      \
                cp_async16(a_base + (uint32_t)(((buf) * BM * AS_STRIDE +                    \
                                (idx >> 2) * AS_STRIDE + (idx & 3) * 4) * 4),               \
                           Ap + (size_t)(idx >> 2) * K + (k0) + (idx & 3) * 4);             \
            }                                                                               \
            _Pragma("unroll")                                                               \
            for (int i = 0; i < 2; i++) {                                                   \
                int idx = t + 256 * i;                                                      \
                cp_async16(b_base + (uint32_t)(((buf) * 16 * BS_STRIDE +                    \
                                (idx >> 5) * BS_STRIDE + (idx & 31) * 4) * 4),              \
                           Bp + (size_t)((k0) + (idx >> 5)) * N + (idx & 31) * 4);          \
            }                                                                               \
            asm volatile("cp.async.commit_group;");                                        \
        }

    const int NK = K / 16;
    #pragma unroll
    for (int s = 0; s < GEMM_STAGES - 1; s++) ISSUE_TILE(s * 16, s);

    for (int it = 0; it < NK; it++) {
        asm volatile("cp.async.wait_group %0;" :: "n"(GEMM_STAGES - 2));
        __syncthreads();
        int nf = it + GEMM_STAGES - 1;
        if (nf < NK) {
            ISSUE_TILE(nf * 16, nf & (GEMM_STAGES - 1));
        } else {
            asm volatile("cp.async.commit_group;");
        }
        const uint32_t* Asb = As + (it & (GEMM_STAGES - 1)) * BM * AS_STRIDE;
        const uint32_t* Bsb = Bs + (it & (GEMM_STAGES - 1)) * 16 * BS_STRIDE;
        #pragma unroll
        for (int ks = 0; ks < 2; ks++) {
            uint32_t af[2][4];
            #pragma unroll
            for (int mt = 0; mt < 2; mt++) {
                const uint32_t* ab = &Asb[(wm * 32 + mt * 16 + g) * AS_STRIDE + ks * 8 + tg];
                af[mt][0] = ab[0];
                af[mt][1] = ab[8 * AS_STRIDE];
                af[mt][2] = ab[4];
                af[mt][3] = ab[8 * AS_STRIDE + 4];
            }
            #pragma unroll
            for (int nt = 0; nt < NT; nt++) {
                const uint32_t* bb = &Bsb[(ks * 8 + tg) * BS_STRIDE + wn * WN_OFF + nt * 8 + g];
                uint32_t b0 = bb[0];
                uint32_t b1 = bb[4 * BS_STRIDE];
                #pragma unroll
                for (int mt = 0; mt < 2; mt++) mma_tf32(acc[mt][nt], af[mt], b0, b1);
            }
        }
    }

    // ---- epilogue ----
    #pragma unroll
    for (int mt = 0; mt < 2; mt++) {
        int r0 = m0 + wm * 32 + mt * 16 + g;
        int r1 = r0 + 8;
        #pragma unroll
        for (int nt = 0; nt < NT; nt++) {
            int col = n0 + wn * WN_OFF + nt * 8 + tg * 2;
            float b0 = bias[col], b1 = bias[col + 1];
            float v0 = acc[mt][nt][0] + b0;
            float v1 = acc[mt][nt][1] + b1;
            float v2 = acc[mt][nt][2] + b0;
            float v3 = acc[mt][nt][3] + b1;
            if (MODE == 1) {
                v0 = f2tf_f(v0 / (1.f + __expf(-1.702f * v0)));
                v1 = f2tf_f(v1 / (1.f + __expf(-1.702f * v1)));
                v2 = f2tf_f(v2 / (1.f + __expf(-1.702f * v2)));
                v3 = f2tf_f(v3 / (1.f + __expf(-1.702f * v3)));
            }
            if (MODE == 2) {
                float2 rr0 = *(const float2*)&R[(size_t)r0 * N + col];
                float2 rr1 = *(const float2*)&R[(size_t)r1 * N + col];
                v0 += rr0.x; v1 += rr0.y; v2 += rr1.x; v3 += rr1.y;
            }
            *(float2*)&C[(size_t)r0 * N + col] = make_float2(v0, v1);
            *(float2*)&C[(size_t)r1 * N + col] = make_float2(v2, v3);
        }
    }
}

// ---------------- RoPE + head split ----------------
__global__ __launch_bounds__(256) void rope_kernel(const float* __restrict__ qkv,
                                                   const float* __restrict__ cosp,
                                                   const float* __restrict__ sinp,
                                                   float* __restrict__ q,
                                                   float* __restrict__ k,
                                                   float* __restrict__ v) {
    int idx = blockIdx.x * 256 + threadIdx.x;
    if (idx >= S_ * H_ * D_) return;
    int d = idx % D_;
    int h = (idx / D_) % H_;
    int s = idx / (H_ * D_);
    float c = cosp[s * D_ + d], sn = sinp[s * D_ + d];
    size_t base = (size_t)s * E3_ + h * D_;
    float qv = qkv[base + d];
    float kv = qkv[base + E_ + d];
    float vv = qkv[base + 2 * E_ + d];
    int dro = (d < 40) ? d + 40 : d - 40;
    float sgn = (d < 40) ? -1.f : 1.f;
    float qr = sgn * qkv[base + dro];
    float kr = sgn * qkv[base + E_ + dro];
    size_t o = ((size_t)h * S_ + s) * D_ + d;
    q[o] = qv * c + qr * sn;
    k[o] = kv * c + kr * sn;
    v[o] = vv;
}

// ---------------- Tensor-core flash attention (tf32 mma, online softmax) ----------------
#define QS 84
#define VS 88
#define PS 68
#define ATTN_SMEM_WORDS (64*QS + 64*QS + 64*VS + 64*PS + 448)
#define ATTN_SMEM_BYTES (ATTN_SMEM_WORDS * 4)

__global__ __launch_bounds__(256) void attn_tc(const float* __restrict__ Q,
                                               const float* __restrict__ K,
                                               const float* __restrict__ V,
                                               float* __restrict__ out) {
    extern __shared__ uint32_t sm[];
    uint32_t* Qs = sm;
    uint32_t* Ks = Qs + 64 * QS;
    uint32_t* Vs = Ks + 64 * QS;
    uint32_t* Ps = Vs + 64 * VS;
    float* mrow = (float*)(Ps + 64 * PS);
    float* lrow = mrow + 64;
    float* arow = lrow + 64;
    float* pm   = arow + 64;
    float* ps   = pm + 128;

    const int t = threadIdx.x;
    const int warp = t >> 5, lane = t & 31;
    const int g = lane >> 2, tg = lane & 3;
    const int wm = warp >> 1, wn = warp & 1;
    const int h = blockIdx.y;
    const int q0 = blockIdx.x * 64;
    const size_t hb = (size_t)h * S_ * D_;
    const float scale = 0.1118033988749895f;

    #pragma unroll
    for (int i = 0; i < 5; i++) {
        int idx = t + 256 * i;
        int r = idx / 20, c4 = (idx % 20) * 4;
        float4 v = *(const float4*)(Q + hb + (size_t)(q0 + r) * D_ + c4);
        uint4 w = make_uint4(f2tf(v.x * scale), f2tf(v.y * scale),
                             f2tf(v.z * scale), f2tf(v.w * scale));
        *(uint4*)&Qs[r * QS + c4] = w;
    }
    if (t < 64) { mrow[t] = -3.0e38f; lrow[t] = 0.f; }

    float oacc[5][4];
    #pragma unroll
    for (int nt = 0; nt < 5; nt++)
        #pragma unroll
        for (int r = 0; r < 4; r++) oacc[nt][r] = 0.f;

    const int r0 = wm * 16 + g, r1 = r0 + 8;

    for (int k0 = 0; k0 < S_; k0 += 64) {
        __syncthreads();
        #pragma unroll
        for (int i = 0; i < 5; i++) {
            int idx = t + 256 * i;
            int r = idx / 20, c4 = (idx % 20) * 4;
            size_t off = hb + (size_t)(k0 + r) * D_ + c4;
            float4 kv = *(const float4*)(K + off);
            float4 vv = *(const float4*)(V + off);
            *(uint4*)&Ks[r * QS + c4] =
                make_uint4(f2tf(kv.x), f2tf(kv.y), f2tf(kv.z), f2tf(kv.w));
            *(uint4*)&Vs[r * VS + c4] =
                make_uint4(f2tf(vv.x), f2tf(vv.y), f2tf(vv.z), f2tf(vv.w));
        }
        __syncthreads();

        float sacc[4][4];
        #pragma unroll
        for (int nt = 0; nt < 4; nt++)
            #pragma unroll
            for (int r = 0; r < 4; r++) sacc[nt][r] = 0.f;

        #pragma unroll
        for (int ks = 0; ks < 10; ks++) {
            uint32_t af[4];
            const uint32_t* ab = &Qs[r0 * QS + ks * 8 + tg];
            af[0] = ab[0];
            af[1] = ab[8 * QS];
            af[2] = ab[4];
            af[3] = ab[8 * QS + 4];
            #pragma unroll
            for (int nt = 0; nt < 4; nt++) {
                const uint32_t* bb = &Ks[(wn * 32 + nt * 8 + g) * QS + ks * 8 + tg];
                mma_tf32(sacc[nt], af, bb[0], bb[4]);
            }
        }

        float m0 = -3.0e38f, m1 = -3.0e38f;
        #pragma unroll
        for (int nt = 0; nt < 4; nt++) {
            m0 = fmaxf(m0, fmaxf(sacc[nt][0], sacc[nt][1]));
            m1 = fmaxf(m1, fmaxf(sacc[nt][2], sacc[nt][3]));
        }
        m0 = fmaxf(m0, __shfl_xor_sync(0xffffffffu, m0, 1));
        m0 = fmaxf(m0, __shfl_xor_sync(0xffffffffu, m0, 2));
        m1 = fmaxf(m1, __shfl_xor_sync(0xffffffffu, m1, 1));
        m1 = fmaxf(m1, __shfl_xor_sync(0xffffffffu, m1, 2));
        if (tg == 0) { pm[r0 * 2 + wn] = m0; pm[r1 * 2 + wn] = m1; }
        __syncthreads();

        if (t < 64) {
            float mn = fmaxf(mrow[t], fmaxf(pm[t * 2], pm[t * 2 + 1]));
            arow[t] = __expf(mrow[t] - mn);
            mrow[t] = mn;
        }
        __syncthreads();

        float mv0 = mrow[r0], mv1 = mrow[r1];
        float s0 = 0.f, s1 = 0.f;
        #pragma unroll
        for (int nt = 0; nt < 4; nt++) {
            float e0 = __expf(sacc[nt][0] - mv0);
            float e1 = __expf(sacc[nt][1] - mv0);
            float e2 = __expf(sacc[nt][2] - mv1);
            float e3 = __expf(sacc[nt][3] - mv1);
            s0 += e0 + e1; s1 += e2 + e3;
            int cb = wn * 32 + nt * 8 + 2 * tg;
            *(uint2*)&Ps[r0 * PS + cb] = make_uint2(f2tf(e0), f2tf(e1));
            *(uint2*)&Ps[r1 * PS + cb] = make_uint2(f2tf(e2), f2tf(e3));
        }
        s0 += __shfl_xor_sync(0xffffffffu, s0, 1);
        s0 += __shfl_xor_sync(0xffffffffu, s0, 2);
        s1 += __shfl_xor_sync(0xffffffffu, s1, 1);
        s1 += __shfl_xor_sync(0xffffffffu, s1, 2);
        if (tg == 0) { ps[r0 * 2 + wn] = s0; ps[r1 * 2 + wn] = s1; }

        float a0 = arow[r0], a1 = arow[r1];
        #pragma unroll
        for (int nt = 0; nt < 5; nt++) {
            oacc[nt][0] *= a0; oacc[nt][1] *= a0;
            oacc[nt][2] *= a1; oacc[nt][3] *= a1;
        }
        __syncthreads();

        if (t < 64) lrow[t] = lrow[t] * arow[t] + ps[t * 2] + ps[t * 2 + 1];

        #pragma unroll
        for (int kc = 0; kc < 8; kc++) {
            uint32_t af[4];
            const uint32_t* ab = &Ps[r0 * PS + kc * 8 + tg];
            af[0] = ab[0];
            af[1] = ab[8 * PS];
            af[2] = ab[4];
            af[3] = ab[8 * PS + 4];
            #pragma unroll
            for (int nt = 0; nt < 5; nt++) {
                const uint32_t* bb = &Vs[(kc * 8 + tg) * VS + wn * 40 + nt * 8 + g];
                mma_tf32(oacc[nt], af, bb[0], bb[4 * VS]);
            }
        }
    }
    __syncthreads();

    float inv0 = 1.f / lrow[r0], inv1 = 1.f / lrow[r1];
    #pragma unroll
    for (int nt = 0; nt < 5; nt++) {
        int col = h * D_ + wn * 40 + nt * 8 + 2 * tg;
        // round: this buffer is an A operand of the WO GEMM
        *(float2*)&out[(size_t)(q0 + r0) * E_ + col] =
            make_float2(f2tf_f(oacc[nt][0] * inv0), f2tf_f(oacc[nt][1] * inv0));
        *(float2*)&out[(size_t)(q0 + r1) * E_ + col] =
            make_float2(f2tf_f(oacc[nt][2] * inv1), f2tf_f(oacc[nt][3] * inv1));
    }
}

// ---------------- launch ----------------
extern "C" void kernel_launch(void* const* d_in, const int* in_sizes, int n_in,
                              void* d_out, int out_size) {
    const float* x    = (const float*)d_in[0];
    // d_in[1] = attention_mask (all true) — unused
    const float* cosp = (const float*)d_in[2];
    const float* sinp = (const float*)d_in[3];
    const float* ln1g = (const float*)d_in[4];
    const float* ln1b = (const float*)d_in[5];
    const float* ln2g = (const float*)d_in[6];
    const float* ln2b = (const float*)d_in[7];
    const float* wqkv = (const float*)d_in[8];
    const float* bqkv = (const float*)d_in[9];
    const float* wo   = (const float*)d_in[10];
    const float* bo   = (const float*)d_in[11];
    const float* wfc1 = (const float*)d_in[12];
    const float* bfc1 = (const float*)d_in[13];
    const float* wfc2 = (const float*)d_in[14];
    const float* bfc2 = (const float*)d_in[15];
    float* out = (float*)d_out;

    float *lnp, *qkvp, *qp, *kp, *vp, *attnp, *x1p, *ln2p, *fc1p;
    float *wqkv_r, *wo_r, *wfc1_r, *wfc2_r;
    cudaGetSymbolAddress((void**)&lnp,   g_ln);
    cudaGetSymbolAddress((void**)&qkvp,  g_qkv);
    cudaGetSymbolAddress((void**)&qp,    g_q);
    cudaGetSymbolAddress((void**)&kp,    g_k);
    cudaGetSymbolAddress((void**)&vp,    g_v);
    cudaGetSymbolAddress((void**)&attnp, g_attn);
    cudaGetSymbolAddress((void**)&x1p,   g_x1);
    cudaGetSymbolAddress((void**)&ln2p,  g_ln2);
    cudaGetSymbolAddress((void**)&fc1p,  g_fc1);
    cudaGetSymbolAddress((void**)&wqkv_r, g_wqkv_r);
    cudaGetSymbolAddress((void**)&wo_r,   g_wo_r);
    cudaGetSymbolAddress((void**)&wfc1_r, g_wfc1_r);
    cudaGetSymbolAddress((void**)&wfc2_r, g_wfc2_r);

    cudaFuncSetAttribute(attn_tc, cudaFuncAttributeMaxDynamicSharedMemorySize,
                         ATTN_SMEM_BYTES);
    cudaFuncSetAttribute((gemm_tf32<0,128>), cudaFuncAttributeMaxDynamicSharedMemorySize,
                         GEMM_SMEM_BYTES(128));
    cudaFuncSetAttribute((gemm_tf32<1,128>), cudaFuncAttributeMaxDynamicSharedMemorySize,
                         GEMM_SMEM_BYTES(128));
    cudaFuncSetAttribute((gemm_tf32<2,64>), cudaFuncAttributeMaxDynamicSharedMemorySize,
                         GEMM_SMEM_BYTES(64));

    // 0. weight pre-round to exact tf32 values (rna)
    round_tf32<<<(E_ * E3_) / 1024, 256>>>(wqkv, wqkv_r);
    round_tf32<<<(E_ * E_)  / 1024, 256>>>(wo,   wo_r);
    round_tf32<<<(E_ * F_)  / 1024, 256>>>(wfc1, wfc1_r);
    round_tf32<<<(F_ * E_)  / 1024, 256>>>(wfc2, wfc2_r);

    // 1. LN1 (tf32-rounded output)
    ln_kernel<<<S_, 256>>>(x, ln1g, ln1b, lnp);
    // 2. QKV = ln1 @ w_qkv + b_qkv      [2048,1280]x[1280,3840]
    gemm_tf32<0,128><<<dim3(E3_ / 128, S_ / 128), 256, GEMM_SMEM_BYTES(128)>>>(
        lnp, wqkv_r, bqkv, nullptr, qkvp, S_, E3_, E_);
    // 3. RoPE + split into head-major q/k/v
    rope_kernel<<<(S_ * H_ * D_) / 256, 256>>>(qkvp, cosp, sinp, qp, kp, vp);
    // 4. Attention (tensor-core flash), tf32-rounded output
    attn_tc<<<dim3(S_ / 64, H_), 256, ATTN_SMEM_BYTES>>>(qp, kp, vp, attnp);
    // 5. x1 = x + attn @ w_o + b_o   (BM=64: 320 CTAs)
    gemm_tf32<2,64><<<dim3(E_ / 128, S_ / 64), 256, GEMM_SMEM_BYTES(64)>>>(
        attnp, wo_r, bo, x, x1p, S_, E_, E_);
    // 6. LN2 (tf32-rounded output)
    ln_kernel<<<S_, 256>>>(x1p, ln2g, ln2b, ln2p);
    // 7. fc1 = quickgelu(ln2 @ w_fc1 + b_fc1), tf32-rounded output
    gemm_tf32<1,128><<<dim3(F_ / 128, S_ / 128), 256, GEMM_SMEM_BYTES(128)>>>(
        ln2p, wfc1_r, bfc1, nullptr, fc1p, S_, F_, E_);
    // 8. out = x1 + fc1 @ w_fc2 + b_fc2   (BM=64: 320 CTAs)
    gemm_tf32<2,64><<<dim3(E_ / 128, S_ / 64), 256, GEMM_SMEM_BYTES(64)>>>(
        fc1p, wfc2_r, bfc2, x1p, out, S_, E_, F_);
}

// round 17
// speedup vs baseline: 1.9924x; 1.0169x over previous
#include <cuda_runtime.h>
#include <stdint.h>
#include <math.h>

#define S_ 2048
#define E_ 1280
#define H_ 16
#define D_ 80
#define F_ 5120
#define E3_ 3840

// ---------------- scratch (device globals; no runtime allocation) ----------------
__device__ float g_ln[S_ * E_];
__device__ float g_qkv[S_ * E3_];
__device__ float g_q[H_ * S_ * D_];
__device__ float g_k[H_ * S_ * D_];
__device__ float g_v[H_ * S_ * D_];
__device__ float g_attn[S_ * E_];
__device__ float g_x1[S_ * E_];
__device__ float g_ln2[S_ * E_];
__device__ float g_fc1[S_ * F_];
// tf32-rounded weight copies (rounded every launch; deterministic)
__device__ float g_wqkv_r[E_ * E3_];
__device__ float g_wo_r[E_ * E_];
__device__ float g_wfc1_r[E_ * F_];
__device__ float g_wfc2_r[F_ * E_];

// ---------------- helpers ----------------
__device__ __forceinline__ uint32_t f2tf(float x) {
    uint32_t r;
    asm("cvt.rna.tf32.f32 %0, %1;" : "=r"(r) : "f"(x));
    return r;
}
__device__ __forceinline__ float f2tf_f(float x) { return __uint_as_float(f2tf(x)); }

__device__ __forceinline__ void mma_tf32(float* c, const uint32_t* a, uint32_t b0, uint32_t b1) {
    asm volatile(
        "mma.sync.aligned.m16n8k8.row.col.f32.tf32.tf32.f32 "
        "{%0,%1,%2,%3}, {%4,%5,%6,%7}, {%8,%9}, {%0,%1,%2,%3};\n"
        : "+f"(c[0]), "+f"(c[1]), "+f"(c[2]), "+f"(c[3])
        : "r"(a[0]), "r"(a[1]), "r"(a[2]), "r"(a[3]), "r"(b0), "r"(b1));
}

__device__ __forceinline__ void cp_async16(uint32_t dst, const float* src) {
    asm volatile("cp.async.cg.shared.global [%0], [%1], 16;\n" :: "r"(dst), "l"(src));
}

// ---------------- weight pre-round (fp32 -> exact tf32 values, rna) ----------------
// 16 elements per thread (4x float4) for MLP=4.
__global__ __launch_bounds__(256) void round_tf32(const float* __restrict__ in,
                                                  float* __restrict__ out) {
    int base = (blockIdx.x * 256 + threadIdx.x) * 16;
    float4 v[4];
    #pragma unroll
    for (int j = 0; j < 4; j++) v[j] = *(const float4*)(in + base + j * 4);
    #pragma unroll
    for (int j = 0; j < 4; j++) {
        uint4 w = make_uint4(f2tf(v[j].x), f2tf(v[j].y), f2tf(v[j].z), f2tf(v[j].w));
        *(uint4*)(out + base + j * 4) = w;
    }
}

// ---------------- LayerNorm (output rounded to tf32 values) ----------------
__global__ __launch_bounds__(256) void ln_kernel(const float* __restrict__ x,
                                                 const float* __restrict__ g,
                                                 const float* __restrict__ b,
                                                 float* __restrict__ out) {
    int row = blockIdx.x;
    const float* xr = x + (size_t)row * E_;
    float s = 0.f, s2 = 0.f;
    for (int i = threadIdx.x; i < E_; i += 256) {
        float v = xr[i];
        s += v; s2 += v * v;
    }
    __shared__ float sh[32];
    #pragma unroll
    for (int o = 16; o > 0; o >>= 1) {
        s  += __shfl_down_sync(0xffffffffu, s, o);
        s2 += __shfl_down_sync(0xffffffffu, s2, o);
    }
    int w = threadIdx.x >> 5, l = threadIdx.x & 31;
    if (l == 0) { sh[w] = s; sh[w + 8] = s2; }
    __syncthreads();
    if (threadIdx.x == 0) {
        float ts = 0.f, ts2 = 0.f;
        #pragma unroll
        for (int i = 0; i < 8; i++) { ts += sh[i]; ts2 += sh[i + 8]; }
        float mean = ts / E_;
        float var = ts2 / E_ - mean * mean;
        sh[16] = mean;
        sh[17] = rsqrtf(var + 1e-6f);
    }
    __syncthreads();
    float mean = sh[16], inv = sh[17];
    for (int i = threadIdx.x; i < E_; i += 256) {
        out[(size_t)row * E_ + i] = f2tf_f((xr[i] - mean) * inv * g[i] + b[i]);
    }
}

// ---------------- tf32 tensor-core GEMM, 4-stage cp.async pipeline ----------------
// C[M,N] = A[M,K] @ B[K,N] + bias (+epilogue). Operands must be exact tf32 values.
// MODE 0: bias. MODE 1: bias + quickGELU (output tf32-rounded). MODE 2: bias + residual R.
// BM=128: 128x128 tile, warp 32x64 (occ 2). BM=64: 64x128 tile, warp 32x32 (occ 3).
#define AS_STRIDE 20
#define BS_STRIDE 136
#define GEMM_STAGES 4
#define GEMM_SMEM_WORDS(BM) (GEMM_STAGES * ((BM) * AS_STRIDE + 16 * BS_STRIDE))
#define GEMM_SMEM_BYTES(BM) (GEMM_SMEM_WORDS(BM) * 4)

template <int MODE, int BM>
__global__ __launch_bounds__(256, (BM == 64 ? 3 : 2))
void gemm_tf32(const float* __restrict__ A,
               const float* __restrict__ B,
               const float* __restrict__ bias,
               const float* __restrict__ R,
               float* __restrict__ C,
               int M, int N, int K) {
    extern __shared__ uint32_t gsm[];
    uint32_t* As = gsm;                                      // [STAGES][BM*AS_STRIDE]
    uint32_t* Bs = gsm + GEMM_STAGES * BM * AS_STRIDE;       // [STAGES][16*BS_STRIDE]

    constexpr int NT = (BM == 128) ? 8 : 4;
    constexpr int WN_OFF = (BM == 128) ? 64 : 32;
    constexpr int A_ITERS = BM / 64;

    const int t = threadIdx.x;
    const int warp = t >> 5, lane = t & 31;
    const int g = lane >> 2, tg = lane & 3;
    const int wm = (BM == 128) ? (warp >> 1) : (warp >> 2);
    const int wn = (BM == 128) ? (warp & 1) : (warp & 3);
    const int m0 = blockIdx.y * BM, n0 = blockIdx.x * 128;

    float acc[2][NT][4];
    #pragma unroll
    for (int mt = 0; mt < 2; mt++)
        #pragma unroll
        for (int nt = 0; nt < NT; nt++)
            #pragma unroll
            for (int r = 0; r < 4; r++) acc[mt][nt][r] = 0.f;

    const float* Ap = A + (size_t)m0 * K;
    const float* Bp = B + n0;
    const uint32_t a_base = (uint32_t)__cvta_generic_to_shared(As);
    const uint32_t b_base = (uint32_t)__cvta_generic_to_shared(Bs);

    #define ISSUE_TILE(k0, buf)                                                             \
        {                                                                                   \
            _Pragma("unroll")                                                               \
            for (int i = 0; i < A_ITERS; i++) {                                             \
                int idx = t + 256 * i;                                                      \
                cp_async16(a_base + (uint32_t)(((buf) * BM * AS_STRIDE +                    \
                                (idx >> 2) * AS_STRIDE + (idx & 3) * 4) * 4),               \
                           Ap + (size_t)(idx >> 2) * K + (k0) + (idx & 3) * 4);             \
            }                                                                               \
            _Pragma("unroll")                                                               \
            for (int i = 0; i < 2; i++) {                                                   \
                int idx = t + 256 * i;                                                      \
                cp_async16(b_base + (uint32_t)(((buf) * 16 * BS_STRIDE +                    \
                                (idx >> 5) * BS_STRIDE + (idx & 31) * 4) * 4),              \
                           Bp + (size_t)((k0) + (idx >> 5)) * N + (idx & 31) * 4);          \
            }                                                                               \
            asm volatile("cp.async.commit_group;");                                        \
        }

    const int NK = K / 16;
    #pragma unroll
    for (int s = 0; s < GEMM_STAGES - 1; s++) ISSUE_TILE(s * 16, s);

    for (int it = 0; it < NK; it++) {
        asm volatile("cp.async.wait_group %0;" :: "n"(GEMM_STAGES - 2));
        __syncthreads();
        int nf = it + GEMM_STAGES - 1;
        if (nf < NK) {
            ISSUE_TILE(nf * 16, nf & (GEMM_STAGES - 1));
        } else {
            asm volatile("cp.async.commit_group;");
        }
        const uint32_t* Asb = As + (it & (GEMM_STAGES - 1)) * BM * AS_STRIDE;
        const uint32_t* Bsb = Bs + (it & (GEMM_STAGES - 1)) * 16 * BS_STRIDE;
        #pragma unroll
        for (int ks = 0; ks < 2; ks++) {
            uint32_t af[2][4];
            #pragma unroll
            for (int mt = 0; mt < 2; mt++) {
                const uint32_t* ab = &Asb[(wm * 32 + mt * 16 + g) * AS_STRIDE + ks * 8 + tg];
                af[mt][0] = ab[0];
                af[mt][1] = ab[8 * AS_STRIDE];
                af[mt][2] = ab[4];
                af[mt][3] = ab[8 * AS_STRIDE + 4];
            }
            #pragma unroll
            for (int nt = 0; nt < NT; nt++) {
                const uint32_t* bb = &Bsb[(ks * 8 + tg) * BS_STRIDE + wn * WN_OFF + nt * 8 + g];
                uint32_t b0 = bb[0];
                uint32_t b1 = bb[4 * BS_STRIDE];
                #pragma unroll
                for (int mt = 0; mt < 2; mt++) mma_tf32(acc[mt][nt], af[mt], b0, b1);
            }
        }
    }

    // ---- epilogue ----
    #pragma unroll
    for (int mt = 0; mt < 2; mt++) {
        int r0 = m0 + wm * 32 + mt * 16 + g;
        int r1 = r0 + 8;
        #pragma unroll
        for (int nt = 0; nt < NT; nt++) {
            int col = n0 + wn * WN_OFF + nt * 8 + tg * 2;
            float b0 = bias[col], b1 = bias[col + 1];
            float v0 = acc[mt][nt][0] + b0;
            float v1 = acc[mt][nt][1] + b1;
            float v2 = acc[mt][nt][2] + b0;
            float v3 = acc[mt][nt][3] + b1;
            if (MODE == 1) {
                v0 = f2tf_f(v0 / (1.f + __expf(-1.702f * v0)));
                v1 = f2tf_f(v1 / (1.f + __expf(-1.702f * v1)));
                v2 = f2tf_f(v2 / (1.f + __expf(-1.702f * v2)));
                v3 = f2tf_f(v3 / (1.f + __expf(-1.702f * v3)));
            }
            if (MODE == 2) {
                float2 rr0 = *(const float2*)&R[(size_t)r0 * N + col];
                float2 rr1 = *(const float2*)&R[(size_t)r1 * N + col];
                v0 += rr0.x; v1 += rr0.y; v2 += rr1.x; v3 += rr1.y;
            }
            *(float2*)&C[(size_t)r0 * N + col] = make_float2(v0, v1);
            *(float2*)&C[(size_t)r1 * N + col] = make_float2(v2, v3);
        }
    }
}

// ---------------- RoPE + head split (outputs exact tf32 values; q pre-scaled) ----------------
__global__ __launch_bounds__(256) void rope_kernel(const float* __restrict__ qkv,
                                                   const float* __restrict__ cosp,
                                                   const float* __restrict__ sinp,
                                                   float* __restrict__ q,
                                                   float* __restrict__ k,
                                                   float* __restrict__ v) {
    int idx = blockIdx.x * 256 + threadIdx.x;
    if (idx >= S_ * H_ * D_) return;
    int d = idx % D_;
    int h = (idx / D_) % H_;
    int s = idx / (H_ * D_);
    const float scale = 0.1118033988749895f;  // 1/sqrt(80)
    float c = cosp[s * D_ + d], sn = sinp[s * D_ + d];
    size_t base = (size_t)s * E3_ + h * D_;
    float qv = qkv[base + d];
    float kv = qkv[base + E_ + d];
    float vv = qkv[base + 2 * E_ + d];
    int dro = (d < 40) ? d + 40 : d - 40;
    float sgn = (d < 40) ? -1.f : 1.f;
    float qr = sgn * qkv[base + dro];
    float kr = sgn * qkv[base + E_ + dro];
    size_t o = ((size_t)h * S_ + s) * D_ + d;
    q[o] = f2tf_f((qv * c + qr * sn) * scale);
    k[o] = f2tf_f(kv * c + kr * sn);
    v[o] = f2tf_f(vv);
}

// ---------------- Tensor-core flash attention (tf32 mma, online softmax) ----------------
// cp.async loads (Q/K/V pre-rounded tf32, Q pre-scaled), register-resident m/l,
// 3 barriers per tile. V load (group) overlaps QK mma + softmax.
#define QS 84
#define VS 88
#define PS 68
#define ATTN_SMEM_WORDS (64*QS + 64*QS + 64*VS + 64*PS + 256)
#define ATTN_SMEM_BYTES (ATTN_SMEM_WORDS * 4)

__global__ __launch_bounds__(256) void attn_tc(const float* __restrict__ Q,
                                               const float* __restrict__ K,
                                               const float* __restrict__ V,
                                               float* __restrict__ out) {
    extern __shared__ uint32_t sm[];
    uint32_t* Qs = sm;
    uint32_t* Ks = Qs + 64 * QS;
    uint32_t* Vs = Ks + 64 * QS;
    uint32_t* Ps = Vs + 64 * VS;
    float* pm = (float*)(Ps + 64 * PS);   // [64][2] max partials
    float* ps = pm + 128;                  // [64][2] sum partials

    const int t = threadIdx.x;
    const int warp = t >> 5, lane = t & 31;
    const int g = lane >> 2, tg = lane & 3;
    const int wm = warp >> 1, wn = warp & 1;
    const int h = blockIdx.y;
    const int q0 = blockIdx.x * 64;
    const size_t hb = (size_t)h * S_ * D_;

    const uint32_t qs_b = (uint32_t)__cvta_generic_to_shared(Qs);
    const uint32_t ks_b = (uint32_t)__cvta_generic_to_shared(Ks);
    const uint32_t vs_b = (uint32_t)__cvta_generic_to_shared(Vs);

    // Q tile via cp.async (group 0)
    #pragma unroll
    for (int i = 0; i < 5; i++) {
        int idx = t + 256 * i;
        int r = idx / 20, c4 = (idx % 20) * 4;
        cp_async16(qs_b + (uint32_t)((r * QS + c4) * 4),
                   Q + hb + (size_t)(q0 + r) * D_ + c4);
    }
    asm volatile("cp.async.commit_group;");

    float oacc[5][4];
    #pragma unroll
    for (int nt = 0; nt < 5; nt++)
        #pragma unroll
        for (int r = 0; r < 4; r++) oacc[nt][r] = 0.f;

    float m0r = -3.0e38f, m1r = -3.0e38f, l0r = 0.f, l1r = 0.f;
    const int r0 = wm * 16 + g, r1 = r0 + 8;

    for (int k0 = 0; k0 < S_; k0 += 64) {
        __syncthreads();  // Ks/Vs/Ps free (prev tile fully consumed)
        // K tile (own group), then V tile (own group)
        #pragma unroll
        for (int i = 0; i < 5; i++) {
            int idx = t + 256 * i;
            int r = idx / 20, c4 = (idx % 20) * 4;
            cp_async16(ks_b + (uint32_t)((r * QS + c4) * 4),
                       K + hb + (size_t)(k0 + r) * D_ + c4);
        }
        asm volatile("cp.async.commit_group;");
        #pragma unroll
        for (int i = 0; i < 5; i++) {
            int idx = t + 256 * i;
            int r = idx / 20, c4 = (idx % 20) * 4;
            cp_async16(vs_b + (uint32_t)((r * VS + c4) * 4),
                       V + hb + (size_t)(k0 + r) * D_ + c4);
        }
        asm volatile("cp.async.commit_group;");
        asm volatile("cp.async.wait_group 1;");  // Q (+K) landed; V may fly
        __syncthreads();

        // ---- S = Q K^T (Q pre-scaled) ----
        float sacc[4][4];
        #pragma unroll
        for (int nt = 0; nt < 4; nt++)
            #pragma unroll
            for (int r = 0; r < 4; r++) sacc[nt][r] = 0.f;

        #pragma unroll
        for (int ks = 0; ks < 10; ks++) {
            uint32_t af[4];
            const uint32_t* ab = &Qs[r0 * QS + ks * 8 + tg];
            af[0] = ab[0];
            af[1] = ab[8 * QS];
            af[2] = ab[4];
            af[3] = ab[8 * QS + 4];
            #pragma unroll
            for (int nt = 0; nt < 4; nt++) {
                const uint32_t* bb = &Ks[(wn * 32 + nt * 8 + g) * QS + ks * 8 + tg];
                mma_tf32(sacc[nt], af, bb[0], bb[4]);
            }
        }

        // ---- row max partials (quad shuffle over tg), cross-wn via smem ----
        float m0 = -3.0e38f, m1 = -3.0e38f;
        #pragma unroll
        for (int nt = 0; nt < 4; nt++) {
            m0 = fmaxf(m0, fmaxf(sacc[nt][0], sacc[nt][1]));
            m1 = fmaxf(m1, fmaxf(sacc[nt][2], sacc[nt][3]));
        }
        m0 = fmaxf(m0, __shfl_xor_sync(0xffffffffu, m0, 1));
        m0 = fmaxf(m0, __shfl_xor_sync(0xffffffffu, m0, 2));
        m1 = fmaxf(m1, __shfl_xor_sync(0xffffffffu, m1, 1));
        m1 = fmaxf(m1, __shfl_xor_sync(0xffffffffu, m1, 2));
        if (tg == 0) { pm[r0 * 2 + wn] = m0; pm[r1 * 2 + wn] = m1; }
        __syncthreads();

        // ---- register-resident m/alpha (redundant per row group) ----
        float mn0 = fmaxf(m0r, fmaxf(pm[r0 * 2], pm[r0 * 2 + 1]));
        float mn1 = fmaxf(m1r, fmaxf(pm[r1 * 2], pm[r1 * 2 + 1]));
        float a0 = __expf(m0r - mn0);
        float a1 = __expf(m1r - mn1);
        m0r = mn0; m1r = mn1;

        // ---- exp, write P (tf32), row-sum partials, rescale O ----
        float s0 = 0.f, s1 = 0.f;
        #pragma unroll
        for (int nt = 0; nt < 4; nt++) {
            float e0 = __expf(sacc[nt][0] - mn0);
            float e1 = __expf(sacc[nt][1] - mn0);
            float e2 = __expf(sacc[nt][2] - mn1);
            float e3 = __expf(sacc[nt][3] - mn1);
            s0 += e0 + e1; s1 += e2 + e3;
            int cb = wn * 32 + nt * 8 + 2 * tg;
            *(uint2*)&Ps[r0 * PS + cb] = make_uint2(f2tf(e0), f2tf(e1));
            *(uint2*)&Ps[r1 * PS + cb] = make_uint2(f2tf(e2), f2tf(e3));
        }
        s0 += __shfl_xor_sync(0xffffffffu, s0, 1);
        s0 += __shfl_xor_sync(0xffffffffu, s0, 2);
        s1 += __shfl_xor_sync(0xffffffffu, s1, 1);
        s1 += __shfl_xor_sync(0xffffffffu, s1, 2);
        if (tg == 0) { ps[r0 * 2 + wn] = s0; ps[r1 * 2 + wn] = s1; }

        #pragma unroll
        for (int nt = 0; nt < 5; nt++) {
            oacc[nt][0] *= a0; oacc[nt][1] *= a0;
            oacc[nt][2] *= a1; oacc[nt][3] *= a1;
        }
        asm volatile("cp.async.wait_group 0;");  // V landed
        __syncthreads();                          // Ps/ps/V visible

        l0r = l0r * a0 + ps[r0 * 2] + ps[r0 * 2 + 1];
        l1r = l1r * a1 + ps[r1 * 2] + ps[r1 * 2 + 1];

        // ---- O += P V ----
        #pragma unroll
        for (int kc = 0; kc < 8; kc++) {
            uint32_t af[4];
            const uint32_t* ab = &Ps[r0 * PS + kc * 8 + tg];
            af[0] = ab[0];
            af[1] = ab[8 * PS];
            af[2] = ab[4];
            af[3] = ab[8 * PS + 4];
            #pragma unroll
            for (int nt = 0; nt < 5; nt++) {
                const uint32_t* bb = &Vs[(kc * 8 + tg) * VS + wn * 40 + nt * 8 + g];
                mma_tf32(oacc[nt], af, bb[0], bb[4 * VS]);
            }
        }
    }

    float inv0 = 1.f / l0r, inv1 = 1.f / l1r;
    #pragma unroll
    for (int nt = 0; nt < 5; nt++) {
        int col = h * D_ + wn * 40 + nt * 8 + 2 * tg;
        // round: this buffer is an A operand of the WO GEMM
        *(float2*)&out[(size_t)(q0 + r0) * E_ + col] =
            make_float2(f2tf_f(oacc[nt][0] * inv0), f2tf_f(oacc[nt][1] * inv0));
        *(float2*)&out[(size_t)(q0 + r1) * E_ + col] =
            make_float2(f2tf_f(oacc[nt][2] * inv1), f2tf_f(oacc[nt][3] * inv1));
    }
}

// ---------------- launch ----------------
extern "C" void kernel_launch(void* const* d_in, const int* in_sizes, int n_in,
                              void* d_out, int out_size) {
    const float* x    = (const float*)d_in[0];
    // d_in[1] = attention_mask (all true) — unused
    const float* cosp = (const float*)d_in[2];
    const float* sinp = (const float*)d_in[3];
    const float* ln1g = (const float*)d_in[4];
    const float* ln1b = (const float*)d_in[5];
    const float* ln2g = (const float*)d_in[6];
    const float* ln2b = (const float*)d_in[7];
    const float* wqkv = (const float*)d_in[8];
    const float* bqkv = (const float*)d_in[9];
    const float* wo   = (const float*)d_in[10];
    const float* bo   = (const float*)d_in[11];
    const float* wfc1 = (const float*)d_in[12];
    const float* bfc1 = (const float*)d_in[13];
    const float* wfc2 = (const float*)d_in[14];
    const float* bfc2 = (const float*)d_in[15];
    float* out = (float*)d_out;

    float *lnp, *qkvp, *qp, *kp, *vp, *attnp, *x1p, *ln2p, *fc1p;
    float *wqkv_r, *wo_r, *wfc1_r, *wfc2_r;
    cudaGetSymbolAddress((void**)&lnp,   g_ln);
    cudaGetSymbolAddress((void**)&qkvp,  g_qkv);
    cudaGetSymbolAddress((void**)&qp,    g_q);
    cudaGetSymbolAddress((void**)&kp,    g_k);
    cudaGetSymbolAddress((void**)&vp,    g_v);
    cudaGetSymbolAddress((void**)&attnp, g_attn);
    cudaGetSymbolAddress((void**)&x1p,   g_x1);
    cudaGetSymbolAddress((void**)&ln2p,  g_ln2);
    cudaGetSymbolAddress((void**)&fc1p,  g_fc1);
    cudaGetSymbolAddress((void**)&wqkv_r, g_wqkv_r);
    cudaGetSymbolAddress((void**)&wo_r,   g_wo_r);
    cudaGetSymbolAddress((void**)&wfc1_r, g_wfc1_r);
    cudaGetSymbolAddress((void**)&wfc2_r, g_wfc2_r);

    cudaFuncSetAttribute(attn_tc, cudaFuncAttributeMaxDynamicSharedMemorySize,
                         ATTN_SMEM_BYTES);
    cudaFuncSetAttribute((gemm_tf32<0,128>), cudaFuncAttributeMaxDynamicSharedMemorySize,
                         GEMM_SMEM_BYTES(128));
    cudaFuncSetAttribute((gemm_tf32<1,128>), cudaFuncAttributeMaxDynamicSharedMemorySize,
                         GEMM_SMEM_BYTES(128));
    cudaFuncSetAttribute((gemm_tf32<2,64>), cudaFuncAttributeMaxDynamicSharedMemorySize,
                         GEMM_SMEM_BYTES(64));

    // 0. weight pre-round to exact tf32 values (rna); 16 elems/thread
    round_tf32<<<(E_ * E3_) / 4096, 256>>>(wqkv, wqkv_r);
    round_tf32<<<(E_ * E_)  / 4096, 256>>>(wo,   wo_r);
    round_tf32<<<(E_ * F_)  / 4096, 256>>>(wfc1, wfc1_r);
    round_tf32<<<(F_ * E_)  / 4096, 256>>>(wfc2, wfc2_r);

    // 1. LN1 (tf32-rounded output)
    ln_kernel<<<S_, 256>>>(x, ln1g, ln1b, lnp);
    // 2. QKV = ln1 @ w_qkv + b_qkv      [2048,1280]x[1280,3840]
    gemm_tf32<0,128><<<dim3(E3_ / 128, S_ / 128), 256, GEMM_SMEM_BYTES(128)>>>(
        lnp, wqkv_r, bqkv, nullptr, qkvp, S_, E3_, E_);
    // 3. RoPE + split (tf32-rounded q/k/v, q pre-scaled by 1/sqrt(D))
    rope_kernel<<<(S_ * H_ * D_) / 256, 256>>>(qkvp, cosp, sinp, qp, kp, vp);
    // 4. Attention (tensor-core flash, cp.async, register m/l), tf32-rounded output
    attn_tc<<<dim3(S_ / 64, H_), 256, ATTN_SMEM_BYTES>>>(qp, kp, vp, attnp);
    // 5. x1 = x + attn @ w_o + b_o   (BM=64: 320 CTAs)
    gemm_tf32<2,64><<<dim3(E_ / 128, S_ / 64), 256, GEMM_SMEM_BYTES(64)>>>(
        attnp, wo_r, bo, x, x1p, S_, E_, E_);
    // 6. LN2 (tf32-rounded output)
    ln_kernel<<<S_, 256>>>(x1p, ln2g, ln2b, ln2p);
    // 7. fc1 = quickgelu(ln2 @ w_fc1 + b_fc1), tf32-rounded output
    gemm_tf32<1,128><<<dim3(F_ / 128, S_ / 128), 256, GEMM_SMEM_BYTES(128)>>>(
        ln2p, wfc1_r, bfc1, nullptr, fc1p, S_, F_, E_);
    // 8. out = x1 + fc1 @ w_fc2 + b_fc2   (BM=64: 320 CTAs)
    gemm_tf32<2,64><<<dim3(E_ / 128, S_ / 64), 256, GEMM_SMEM_BYTES(64)>>>(
        fc1p, wfc2_r, bfc2, x1p, out, S_, E_, F_);
}